// round 6
// baseline (speedup 1.0000x reference)
#include <cuda_runtime.h>

#define N_NODES  50000
#define N_EDGES  800000
#define N_GRAPHS 128
#define HID      64
#define VOCAB    100
#define LAYERS   3
#define NPB      128                          // nodes per block in mlp kernel
#define CSR_CAP  (N_EDGES + 7 * N_NODES)      // padded CSR capacity

// Scratch (__device__ globals — allocation-free rule).
// Row N_NODES of g_h_a/g_h_b is a permanent ZERO row (never written) used as
// the padded-CSR dummy gather target. Row VOCAB of g_emb_pad likewise.
__device__ float g_h_a[(N_NODES + 1) * HID];
__device__ float g_h_b[(N_NODES + 1) * HID];
__device__ float g_z[N_NODES * HID];
__device__ float g_emb_pad[(VOCAB + 1) * HID];
__device__ int   g_feats_pad[N_NODES + 1];
__device__ int   g_deg[N_NODES];
__device__ int   g_rowptr[N_NODES + 1];
__device__ int   g_pos[N_NODES];
__device__ int   g_csr_src[CSR_CAP];

// ---------------------------------------------------------------------------
// CSR build (rebuilt every call: deterministic, graph-capturable)
// ---------------------------------------------------------------------------
__global__ void hist_kernel(const int* __restrict__ dst) {
    int i = blockIdx.x * blockDim.x + threadIdx.x;
    if (i * 4 >= N_EDGES) return;
    int4 d = ((const int4*)dst)[i];
    atomicAdd(&g_deg[d.x], 1);
    atomicAdd(&g_deg[d.y], 1);
    atomicAdd(&g_deg[d.z], 1);
    atomicAdd(&g_deg[d.w], 1);
}

__global__ void fill_kernel() {
    int i = blockIdx.x * blockDim.x + threadIdx.x;
    if (i * 4 < CSR_CAP)
        ((int4*)g_csr_src)[i] = make_int4(N_NODES, N_NODES, N_NODES, N_NODES);
}

// Scan PADDED degrees (rounded up to multiple of 8) -> rowptr; g_pos = rowptr.
__global__ void __launch_bounds__(1024) scan_kernel() {
    __shared__ int ssum[1024];
    const int CH = (N_NODES + 1023) / 1024;  // 49
    int t = threadIdx.x;
    int beg = t * CH;
    int end = beg + CH; if (end > N_NODES) end = N_NODES;
    int s = 0;
    for (int i = beg; i < end; i++) s += (g_deg[i] + 7) & ~7;
    ssum[t] = s;
    __syncthreads();
    for (int off = 1; off < 1024; off <<= 1) {
        int v = (t >= off) ? ssum[t - off] : 0;
        __syncthreads();
        ssum[t] += v;
        __syncthreads();
    }
    int run = ssum[t] - s;
    for (int i = beg; i < end; i++) {
        g_rowptr[i] = run;
        g_pos[i]    = run;
        run += (g_deg[i] + 7) & ~7;
    }
    if (t == 1023) g_rowptr[N_NODES] = ssum[1023];
}

__global__ void scatter_kernel(const int* __restrict__ src,
                               const int* __restrict__ dst) {
    int i = blockIdx.x * blockDim.x + threadIdx.x;
    if (i * 4 >= N_EDGES) return;
    int4 s = ((const int4*)src)[i];
    int4 d = ((const int4*)dst)[i];
    int p;
    p = atomicAdd(&g_pos[d.x], 1); g_csr_src[p] = s.x;
    p = atomicAdd(&g_pos[d.y], 1); g_csr_src[p] = s.y;
    p = atomicAdd(&g_pos[d.z], 1); g_csr_src[p] = s.z;
    p = atomicAdd(&g_pos[d.w], 1); g_csr_src[p] = s.w;
}

// ---------------------------------------------------------------------------
// Prep: padded emb (zero row VOCAB) + padded feats (feats[N_NODES] = VOCAB)
// ---------------------------------------------------------------------------
__global__ void prep_kernel(const int* __restrict__ feats,
                            const float* __restrict__ emb) {
    int i = blockIdx.x * blockDim.x + threadIdx.x;
    if (i < (VOCAB + 1) * HID)
        g_emb_pad[i] = (i < VOCAB * HID) ? emb[i] : 0.f;
    if (i < N_NODES)       g_feats_pad[i] = __ldg(feats + i);
    else if (i == N_NODES) g_feats_pad[i] = VOCAB;
}

// ---------------------------------------------------------------------------
// Layer-0 aggregation directly from the (L1-resident, 25KB) embedding table:
// z[n] = emb[f[n]] + sum_{s in N(n)} emb[f[s]].  Replaces embed + big gather.
// ---------------------------------------------------------------------------
__global__ void __launch_bounds__(256)
agg0_kernel() {
    int i = blockIdx.x * blockDim.x + threadIdx.x;
    if (i >= N_NODES * 16) return;
    int n = i >> 4;
    int c = i & 15;
    const float4* e4 = (const float4*)g_emb_pad;

    float4 acc = e4[__ldg(&g_feats_pad[n]) * 16 + c];
    int e   = __ldg(&g_rowptr[n]);
    int end = __ldg(&g_rowptr[n + 1]);

    for (; e < end; e += 8) {
        int4 sa = *(const int4*)&g_csr_src[e];
        int4 sb = *(const int4*)&g_csr_src[e + 4];
        int f0 = __ldg(&g_feats_pad[sa.x]);
        int f1 = __ldg(&g_feats_pad[sa.y]);
        int f2 = __ldg(&g_feats_pad[sa.z]);
        int f3 = __ldg(&g_feats_pad[sa.w]);
        int f4 = __ldg(&g_feats_pad[sb.x]);
        int f5 = __ldg(&g_feats_pad[sb.y]);
        int f6 = __ldg(&g_feats_pad[sb.z]);
        int f7 = __ldg(&g_feats_pad[sb.w]);
        float4 v0 = e4[f0 * 16 + c];
        float4 v1 = e4[f1 * 16 + c];
        float4 v2 = e4[f2 * 16 + c];
        float4 v3 = e4[f3 * 16 + c];
        float4 v4 = e4[f4 * 16 + c];
        float4 v5 = e4[f5 * 16 + c];
        float4 v6 = e4[f6 * 16 + c];
        float4 v7 = e4[f7 * 16 + c];
        acc.x += v0.x; acc.y += v0.y; acc.z += v0.z; acc.w += v0.w;
        acc.x += v1.x; acc.y += v1.y; acc.z += v1.z; acc.w += v1.w;
        acc.x += v2.x; acc.y += v2.y; acc.z += v2.z; acc.w += v2.w;
        acc.x += v3.x; acc.y += v3.y; acc.z += v3.z; acc.w += v3.w;
        acc.x += v4.x; acc.y += v4.y; acc.z += v4.z; acc.w += v4.w;
        acc.x += v5.x; acc.y += v5.y; acc.z += v5.z; acc.w += v5.w;
        acc.x += v6.x; acc.y += v6.y; acc.z += v6.z; acc.w += v6.w;
        acc.x += v7.x; acc.y += v7.y; acc.z += v7.z; acc.w += v7.w;
    }
    ((float4*)g_z)[n * 16 + c] = acc;
}

// ---------------------------------------------------------------------------
// Layers 1,2 aggregation: z[n] = h[n] + sum h[s]  (padded CSR, 8-deep batches)
// ---------------------------------------------------------------------------
__global__ void __launch_bounds__(256)
agg_kernel(int layer) {
    const float* hin = (layer & 1) ? g_h_b : g_h_a;
    int i = blockIdx.x * blockDim.x + threadIdx.x;
    if (i >= N_NODES * 16) return;
    int n = i >> 4;
    int c = i & 15;
    const float4* h4 = (const float4*)hin;

    float4 acc = h4[n * 16 + c];
    int e   = __ldg(&g_rowptr[n]);
    int end = __ldg(&g_rowptr[n + 1]);

    for (; e < end; e += 8) {
        int4 sa = *(const int4*)&g_csr_src[e];
        int4 sb = *(const int4*)&g_csr_src[e + 4];
        float4 v0 = h4[sa.x * 16 + c];
        float4 v1 = h4[sa.y * 16 + c];
        float4 v2 = h4[sa.z * 16 + c];
        float4 v3 = h4[sa.w * 16 + c];
        float4 v4 = h4[sb.x * 16 + c];
        float4 v5 = h4[sb.y * 16 + c];
        float4 v6 = h4[sb.z * 16 + c];
        float4 v7 = h4[sb.w * 16 + c];
        acc.x += v0.x; acc.y += v0.y; acc.z += v0.z; acc.w += v0.w;
        acc.x += v1.x; acc.y += v1.y; acc.z += v1.z; acc.w += v1.w;
        acc.x += v2.x; acc.y += v2.y; acc.z += v2.z; acc.w += v2.w;
        acc.x += v3.x; acc.y += v3.y; acc.z += v3.z; acc.w += v3.w;
        acc.x += v4.x; acc.y += v4.y; acc.z += v4.z; acc.w += v4.w;
        acc.x += v5.x; acc.y += v5.y; acc.z += v5.z; acc.w += v5.w;
        acc.x += v6.x; acc.y += v6.y; acc.z += v6.z; acc.w += v6.w;
        acc.x += v7.x; acc.y += v7.y; acc.z += v7.z; acc.w += v7.w;
    }
    ((float4*)g_z)[n * 16 + c] = acc;
}

// ---------------------------------------------------------------------------
// MLP: hout = relu(z@W1+b1)@W2 + b2.   256 threads, 128 nodes/block.
// Thread = 4 nodes x 8 cols (node-paired fma.rn.f32x2).
// On the LAST layer, the pool+head (dot with Wr, atomicAdd per graph) is
// fused here and the global hout store is skipped.
// ---------------------------------------------------------------------------
#define OFF_W1 0
#define OFF_W2 4352
#define OFF_B1 8704
#define OFF_B2 8768
#define OFF_Z  8832
#define WPAD   68
#define ZPAD   132
#define SMEM_BYTES (17280 * 4)

__device__ __forceinline__ unsigned su32(const void* p) {
    return (unsigned)__cvta_generic_to_shared(p);
}
__device__ __forceinline__ unsigned long long dupf(float x) {
    unsigned long long r;
    asm("mov.b64 %0, {%1, %1};" : "=l"(r) : "f"(x));
    return r;
}
#define FMA2(d, a, b) asm("fma.rn.f32x2 %0, %1, %2, %0;" : "+l"(d) : "l"(a), "l"(b))

__global__ void __launch_bounds__(256)
mlp_kernel(const float* __restrict__ W1, const float* __restrict__ b1,
           const float* __restrict__ W2, const float* __restrict__ b2,
           int layer, int last,
           const int* __restrict__ gids, const float* __restrict__ Wr,
           float* __restrict__ out) {
    extern __shared__ __align__(16) float sm[];
    float* hout = (layer & 1) ? g_h_a : g_h_b;
    const int tid = threadIdx.x;
    const int nbase = blockIdx.x * NPB;

    // ---- stage weights/biases ----
    {
        const float4* w1 = (const float4*)(W1 + layer * HID * HID);
        const float4* w2 = (const float4*)(W2 + layer * HID * HID);
        for (int idx = tid; idx < 1024; idx += 256) {
            int r = idx >> 4, c = idx & 15;
            *(float4*)&sm[OFF_W1 + r * WPAD + c * 4] = w1[idx];
            *(float4*)&sm[OFF_W2 + r * WPAD + c * 4] = w2[idx];
        }
        if (tid < HID) {
            sm[OFF_B1 + tid] = b1[layer * HID + tid];
            sm[OFF_B2 + tid] = b2[layer * HID + tid];
        }
    }

    // ---- stage z transposed: sz[k][node]; 2 threads per node ----
    {
        int l = tid >> 1, half = tid & 1;
        int n = nbase + l;
        float v[32];
        if (n < N_NODES) {
            const float4* zr = (const float4*)(g_z + n * HID) + half * 8;
#pragma unroll
            for (int q = 0; q < 8; q++) {
                float4 t4 = zr[q];
                v[4 * q + 0] = t4.x; v[4 * q + 1] = t4.y;
                v[4 * q + 2] = t4.z; v[4 * q + 3] = t4.w;
            }
        } else {
#pragma unroll
            for (int q = 0; q < 32; q++) v[q] = 0.f;
        }
#pragma unroll
        for (int k2 = 0; k2 < 32; k2++)
            sm[OFF_Z + (half * 32 + k2) * ZPAD + l] = v[k2];
    }
    __syncthreads();

    const int jg = tid & 7;          // col group: cols j0..j0+7
    const int ig = tid >> 3;         // node group: nodes i0..i0+3
    const int j0 = jg * 8;
    const int i0 = ig * 4;
    const unsigned zb = su32(sm + OFF_Z);

    unsigned long long acc[2][8];

    // ================= GEMV 1: y = relu(z @ W1 + b1) =================
    {
#pragma unroll
        for (int j = 0; j < 8; j++) {
            unsigned long long bd = dupf(sm[OFF_B1 + j0 + j]);
            acc[0][j] = bd; acc[1][j] = bd;
        }
        unsigned za = zb + i0 * 4;
#pragma unroll 8
        for (int k = 0; k < 64; k++) {
            unsigned long long z0, z1;
            asm("ld.shared.v2.u64 {%0,%1},[%2];" : "=l"(z0), "=l"(z1) : "r"(za));
#pragma unroll
            for (int j = 0; j < 8; j++) {
                unsigned long long wd = dupf(sm[OFF_W1 + k * WPAD + j0 + j]);
                FMA2(acc[0][j], z0, wd);
                FMA2(acc[1][j], z1, wd);
            }
            za += ZPAD * 4;
        }
    }
    __syncthreads();  // all z reads done before overwriting with y

    // relu + store y transposed
    {
#pragma unroll
        for (int p = 0; p < 2; p++) {
#pragma unroll
            for (int j = 0; j < 8; j++) {
                float lo, hi;
                asm("mov.b64 {%0,%1},%2;" : "=f"(lo), "=f"(hi) : "l"(acc[p][j]));
                lo = fmaxf(lo, 0.f);
                hi = fmaxf(hi, 0.f);
                unsigned ya = zb + (unsigned)((j0 + j) * ZPAD + i0 + 2 * p) * 4;
                asm volatile("st.shared.v2.b32 [%0],{%1,%2};"
                             :: "r"(ya), "f"(lo), "f"(hi));
            }
        }
    }
    __syncthreads();

    // ================= GEMV 2: hout = y @ W2 + b2 =================
    {
#pragma unroll
        for (int j = 0; j < 8; j++) {
            unsigned long long bd = dupf(sm[OFF_B2 + j0 + j]);
            acc[0][j] = bd; acc[1][j] = bd;
        }
        unsigned za = zb + i0 * 4;
#pragma unroll 8
        for (int k = 0; k < 64; k++) {
            unsigned long long z0, z1;
            asm("ld.shared.v2.u64 {%0,%1},[%2];" : "=l"(z0), "=l"(z1) : "r"(za));
#pragma unroll
            for (int j = 0; j < 8; j++) {
                unsigned long long wd = dupf(sm[OFF_W2 + k * WPAD + j0 + j]);
                FMA2(acc[0][j], z0, wd);
                FMA2(acc[1][j], z1, wd);
            }
            za += ZPAD * 4;
        }
    }

    if (!last) {
        // store h to gmem
#pragma unroll
        for (int p = 0; p < 2; p++) {
            int n0 = nbase + i0 + 2 * p;
            float lo[8], hi[8];
#pragma unroll
            for (int j = 0; j < 8; j++)
                asm("mov.b64 {%0,%1},%2;" : "=f"(lo[j]), "=f"(hi[j]) : "l"(acc[p][j]));
            if (n0 < N_NODES) {
                float* pn = hout + n0 * HID + j0;
                *(float4*)(pn)     = make_float4(lo[0], lo[1], lo[2], lo[3]);
                *(float4*)(pn + 4) = make_float4(lo[4], lo[5], lo[6], lo[7]);
            }
            if (n0 + 1 < N_NODES) {
                float* pn = hout + (n0 + 1) * HID + j0;
                *(float4*)(pn)     = make_float4(hi[0], hi[1], hi[2], hi[3]);
                *(float4*)(pn + 4) = make_float4(hi[4], hi[5], hi[6], hi[7]);
            }
        }
    } else {
        // fused pool + head: partial dot over this thread's 8 cols, 4 nodes
        float dot[4] = {0.f, 0.f, 0.f, 0.f};
#pragma unroll
        for (int j = 0; j < 8; j++) {
            float wr = __ldg(Wr + j0 + j);
            float lo, hi;
            asm("mov.b64 {%0,%1},%2;" : "=f"(lo), "=f"(hi) : "l"(acc[0][j]));
            dot[0] = fmaf(lo, wr, dot[0]);
            dot[1] = fmaf(hi, wr, dot[1]);
            asm("mov.b64 {%0,%1},%2;" : "=f"(lo), "=f"(hi) : "l"(acc[1][j]));
            dot[2] = fmaf(lo, wr, dot[2]);
            dot[3] = fmaf(hi, wr, dot[3]);
        }
        // reduce across the 8 jg lanes (same ig)
#pragma unroll
        for (int m = 1; m < 8; m <<= 1) {
#pragma unroll
            for (int a = 0; a < 4; a++)
                dot[a] += __shfl_xor_sync(0xffffffffu, dot[a], m);
        }
        if (jg == 0) {
#pragma unroll
            for (int a = 0; a < 4; a++) {
                int n = nbase + i0 + a;
                if (n < N_NODES)
                    atomicAdd(out + __ldg(gids + n), dot[a]);
            }
        }
    }
}

// ---------------------------------------------------------------------------
extern "C" void kernel_launch(void* const* d_in, const int* in_sizes, int n_in,
                              void* d_out, int out_size) {
    const int*   feats = (const int*)d_in[0];
    const int*   src   = (const int*)d_in[1];
    const int*   dst   = (const int*)d_in[2];
    const int*   gids  = (const int*)d_in[3];
    const float* emb   = (const float*)d_in[4];
    const float* W1    = (const float*)d_in[5];
    const float* b1    = (const float*)d_in[6];
    const float* W2    = (const float*)d_in[7];
    const float* b2    = (const float*)d_in[8];
    const float* Wr    = (const float*)d_in[9];
    float* out = (float*)d_out;

    cudaFuncSetAttribute(mlp_kernel,
                         cudaFuncAttributeMaxDynamicSharedMemorySize, SMEM_BYTES);

    // CSR build (padded rows) + prep
    void* deg_ptr = nullptr;
    cudaGetSymbolAddress(&deg_ptr, g_deg);
    cudaMemsetAsync(deg_ptr, 0, N_NODES * sizeof(int));
    cudaMemsetAsync(out, 0, N_GRAPHS * sizeof(float));
    fill_kernel<<<(CSR_CAP / 4 + 255) / 256, 256>>>();
    hist_kernel<<<(N_EDGES / 4 + 255) / 256, 256>>>(dst);
    prep_kernel<<<(N_NODES + 1 + 255) / 256, 256>>>(feats, emb);
    scan_kernel<<<1, 1024>>>();
    scatter_kernel<<<(N_EDGES / 4 + 255) / 256, 256>>>(src, dst);

    // 3 GIN layers
    const int ablk = (N_NODES * 16 + 255) / 256;
    const int mblk = (N_NODES + NPB - 1) / NPB;

    agg0_kernel<<<ablk, 256>>>();
    mlp_kernel<<<mblk, 256, SMEM_BYTES>>>(W1, b1, W2, b2, 0, 0, gids, Wr, out);
    agg_kernel<<<ablk, 256>>>(1);
    mlp_kernel<<<mblk, 256, SMEM_BYTES>>>(W1, b1, W2, b2, 1, 0, gids, Wr, out);
    agg_kernel<<<ablk, 256>>>(2);
    mlp_kernel<<<mblk, 256, SMEM_BYTES>>>(W1, b1, W2, b2, 2, 1, gids, Wr, out);
}

// round 7
// speedup vs baseline: 1.5800x; 1.5800x over previous
#include <cuda_runtime.h>

#define N_NODES  50000
#define N_EDGES  800000
#define N_GRAPHS 128
#define HID      64
#define VOCAB    100
#define LAYERS   3
#define NPB      128                          // nodes per block in mlp kernel
#define CSR_CAP  (N_EDGES + 7 * N_NODES)      // padded CSR capacity
#define SCAN_BLKS ((N_NODES + 1023) / 1024)   // 49

// Scratch (__device__ globals — allocation-free rule).
// Row N_NODES of g_h_a/g_h_b is a permanent ZERO row (never written) used as
// the padded-CSR dummy gather target. Row VOCAB of g_emb_pad likewise.
__device__ float g_h_a[(N_NODES + 1) * HID];
__device__ float g_h_b[(N_NODES + 1) * HID];
__device__ float g_z[N_NODES * HID];
__device__ float g_emb_pad[(VOCAB + 1) * HID];
__device__ int   g_feats_pad[N_NODES + 1];
__device__ int   g_deg[N_NODES];
__device__ int   g_rowptr[N_NODES + 1];
__device__ int   g_pos[N_NODES];
__device__ int   g_bsum[SCAN_BLKS];
__device__ int   g_boff[SCAN_BLKS];
__device__ int   g_csr_src[CSR_CAP];

// ---------------------------------------------------------------------------
// CSR build (rebuilt every call: deterministic, graph-capturable)
// ---------------------------------------------------------------------------
__global__ void hist_kernel(const int* __restrict__ dst) {
    int i = blockIdx.x * blockDim.x + threadIdx.x;
    if (i * 4 >= N_EDGES) return;
    int4 d = ((const int4*)dst)[i];
    atomicAdd(&g_deg[d.x], 1);
    atomicAdd(&g_deg[d.y], 1);
    atomicAdd(&g_deg[d.z], 1);
    atomicAdd(&g_deg[d.w], 1);
}

__global__ void fill_kernel() {
    int i = blockIdx.x * blockDim.x + threadIdx.x;
    if (i * 4 < CSR_CAP)
        ((int4*)g_csr_src)[i] = make_int4(N_NODES, N_NODES, N_NODES, N_NODES);
}

// Phase 1: per-block Hillis-Steele scan of PADDED degrees (1024 nodes/block).
// Writes local exclusive prefix into g_rowptr, block total into g_bsum.
__global__ void __launch_bounds__(1024) scan1_kernel() {
    __shared__ int ssum[1024];
    int t = threadIdx.x;
    int i = blockIdx.x * 1024 + t;
    int d = (i < N_NODES) ? ((g_deg[i] + 7) & ~7) : 0;
    ssum[t] = d;
    __syncthreads();
    for (int off = 1; off < 1024; off <<= 1) {
        int v = (t >= off) ? ssum[t - off] : 0;
        __syncthreads();
        ssum[t] += v;
        __syncthreads();
    }
    if (i <= N_NODES - 1 || i == blockIdx.x * 1024 + t)  // always true; keep simple
        if (i < N_NODES) g_rowptr[i] = ssum[t] - d;      // local exclusive prefix
    if (t == 1023) g_bsum[blockIdx.x] = ssum[1023];
}

// Phase 2: one warp scans the 49 block sums (2 values/lane, shfl scan).
__global__ void scan2_kernel() {
    int t = threadIdx.x;      // 0..31
    int i0 = 2 * t, i1 = 2 * t + 1;
    int v0 = (i0 < SCAN_BLKS) ? g_bsum[i0] : 0;
    int v1 = (i1 < SCAN_BLKS) ? g_bsum[i1] : 0;
    int s = v0 + v1;
    int incl = s;
#pragma unroll
    for (int off = 1; off < 32; off <<= 1) {
        int u = __shfl_up_sync(0xffffffffu, incl, off);
        if (t >= off) incl += u;
    }
    int excl = incl - s;
    if (i0 < SCAN_BLKS) g_boff[i0] = excl;
    if (i1 < SCAN_BLKS) g_boff[i1] = excl + v0;
    if (t == 31) g_rowptr[N_NODES] = incl;  // grand total
}

// Phase 3: add block offsets, copy to g_pos.
__global__ void scan3_kernel() {
    int i = blockIdx.x * blockDim.x + threadIdx.x;
    if (i >= N_NODES) return;
    int r = g_rowptr[i] + g_boff[i >> 10];
    g_rowptr[i] = r;
    g_pos[i]    = r;
}

__global__ void scatter_kernel(const int* __restrict__ src,
                               const int* __restrict__ dst) {
    int i = blockIdx.x * blockDim.x + threadIdx.x;
    if (i * 4 >= N_EDGES) return;
    int4 s = ((const int4*)src)[i];
    int4 d = ((const int4*)dst)[i];
    int p;
    p = atomicAdd(&g_pos[d.x], 1); g_csr_src[p] = s.x;
    p = atomicAdd(&g_pos[d.y], 1); g_csr_src[p] = s.y;
    p = atomicAdd(&g_pos[d.z], 1); g_csr_src[p] = s.z;
    p = atomicAdd(&g_pos[d.w], 1); g_csr_src[p] = s.w;
}

// ---------------------------------------------------------------------------
// Prep: padded emb (zero row VOCAB) + padded feats (feats[N_NODES] = VOCAB)
// ---------------------------------------------------------------------------
__global__ void prep_kernel(const int* __restrict__ feats,
                            const float* __restrict__ emb) {
    int i = blockIdx.x * blockDim.x + threadIdx.x;
    if (i < (VOCAB + 1) * HID)
        g_emb_pad[i] = (i < VOCAB * HID) ? emb[i] : 0.f;
    if (i < N_NODES)       g_feats_pad[i] = __ldg(feats + i);
    else if (i == N_NODES) g_feats_pad[i] = VOCAB;
}

// ---------------------------------------------------------------------------
// Layer-0 aggregation directly from the (L1-resident, 25KB) embedding table:
// z[n] = emb[f[n]] + sum_{s in N(n)} emb[f[s]].
// ---------------------------------------------------------------------------
__global__ void __launch_bounds__(256)
agg0_kernel() {
    int i = blockIdx.x * blockDim.x + threadIdx.x;
    if (i >= N_NODES * 16) return;
    int n = i >> 4;
    int c = i & 15;
    const float4* e4 = (const float4*)g_emb_pad;

    float4 acc = e4[__ldg(&g_feats_pad[n]) * 16 + c];
    int e   = __ldg(&g_rowptr[n]);
    int end = __ldg(&g_rowptr[n + 1]);

    for (; e < end; e += 8) {
        int4 sa = *(const int4*)&g_csr_src[e];
        int4 sb = *(const int4*)&g_csr_src[e + 4];
        int f0 = __ldg(&g_feats_pad[sa.x]);
        int f1 = __ldg(&g_feats_pad[sa.y]);
        int f2 = __ldg(&g_feats_pad[sa.z]);
        int f3 = __ldg(&g_feats_pad[sa.w]);
        int f4 = __ldg(&g_feats_pad[sb.x]);
        int f5 = __ldg(&g_feats_pad[sb.y]);
        int f6 = __ldg(&g_feats_pad[sb.z]);
        int f7 = __ldg(&g_feats_pad[sb.w]);
        float4 v0 = e4[f0 * 16 + c];
        float4 v1 = e4[f1 * 16 + c];
        float4 v2 = e4[f2 * 16 + c];
        float4 v3 = e4[f3 * 16 + c];
        float4 v4 = e4[f4 * 16 + c];
        float4 v5 = e4[f5 * 16 + c];
        float4 v6 = e4[f6 * 16 + c];
        float4 v7 = e4[f7 * 16 + c];
        acc.x += v0.x; acc.y += v0.y; acc.z += v0.z; acc.w += v0.w;
        acc.x += v1.x; acc.y += v1.y; acc.z += v1.z; acc.w += v1.w;
        acc.x += v2.x; acc.y += v2.y; acc.z += v2.z; acc.w += v2.w;
        acc.x += v3.x; acc.y += v3.y; acc.z += v3.z; acc.w += v3.w;
        acc.x += v4.x; acc.y += v4.y; acc.z += v4.z; acc.w += v4.w;
        acc.x += v5.x; acc.y += v5.y; acc.z += v5.z; acc.w += v5.w;
        acc.x += v6.x; acc.y += v6.y; acc.z += v6.z; acc.w += v6.w;
        acc.x += v7.x; acc.y += v7.y; acc.z += v7.z; acc.w += v7.w;
    }
    ((float4*)g_z)[n * 16 + c] = acc;
}

// ---------------------------------------------------------------------------
// Layers 1,2 aggregation: z[n] = h[n] + sum h[s]  (padded CSR, 8-deep batches)
// ---------------------------------------------------------------------------
__global__ void __launch_bounds__(256)
agg_kernel(int layer) {
    const float* hin = (layer & 1) ? g_h_b : g_h_a;
    int i = blockIdx.x * blockDim.x + threadIdx.x;
    if (i >= N_NODES * 16) return;
    int n = i >> 4;
    int c = i & 15;
    const float4* h4 = (const float4*)hin;

    float4 acc = h4[n * 16 + c];
    int e   = __ldg(&g_rowptr[n]);
    int end = __ldg(&g_rowptr[n + 1]);

    for (; e < end; e += 8) {
        int4 sa = *(const int4*)&g_csr_src[e];
        int4 sb = *(const int4*)&g_csr_src[e + 4];
        float4 v0 = h4[sa.x * 16 + c];
        float4 v1 = h4[sa.y * 16 + c];
        float4 v2 = h4[sa.z * 16 + c];
        float4 v3 = h4[sa.w * 16 + c];
        float4 v4 = h4[sb.x * 16 + c];
        float4 v5 = h4[sb.y * 16 + c];
        float4 v6 = h4[sb.z * 16 + c];
        float4 v7 = h4[sb.w * 16 + c];
        acc.x += v0.x; acc.y += v0.y; acc.z += v0.z; acc.w += v0.w;
        acc.x += v1.x; acc.y += v1.y; acc.z += v1.z; acc.w += v1.w;
        acc.x += v2.x; acc.y += v2.y; acc.z += v2.z; acc.w += v2.w;
        acc.x += v3.x; acc.y += v3.y; acc.z += v3.z; acc.w += v3.w;
        acc.x += v4.x; acc.y += v4.y; acc.z += v4.z; acc.w += v4.w;
        acc.x += v5.x; acc.y += v5.y; acc.z += v5.z; acc.w += v5.w;
        acc.x += v6.x; acc.y += v6.y; acc.z += v6.z; acc.w += v6.w;
        acc.x += v7.x; acc.y += v7.y; acc.z += v7.z; acc.w += v7.w;
    }
    ((float4*)g_z)[n * 16 + c] = acc;
}

// ---------------------------------------------------------------------------
// MLP: hout = relu(z@W1+b1)@W2 + b2
// 128 threads, 128 nodes/block. Thread = 8 nodes x 8 cols (node-paired fma2).
// On the LAST layer the pool+head is fused (dot with Wr + atomicAdd per
// graph) and the global hout store is skipped.
// ---------------------------------------------------------------------------
#define OFF_W1 0
#define OFF_W2 4352
#define OFF_B1 8704
#define OFF_B2 8768
#define OFF_Z  8832
#define WPAD   68
#define ZPAD   132
#define SMEM_BYTES (17280 * 4)

__device__ __forceinline__ unsigned su32(const void* p) {
    return (unsigned)__cvta_generic_to_shared(p);
}
__device__ __forceinline__ unsigned long long dupf(float x) {
    unsigned long long r;
    asm("mov.b64 %0, {%1, %1};" : "=l"(r) : "f"(x));
    return r;
}
#define FMA2(d, a, b) asm("fma.rn.f32x2 %0, %1, %2, %0;" : "+l"(d) : "l"(a), "l"(b))

__global__ void __launch_bounds__(128)
mlp_kernel(const float* __restrict__ W1, const float* __restrict__ b1,
           const float* __restrict__ W2, const float* __restrict__ b2,
           int layer, int last,
           const int* __restrict__ gids, const float* __restrict__ Wr,
           float* __restrict__ out) {
    extern __shared__ __align__(16) float sm[];
    float* hout = (layer & 1) ? g_h_a : g_h_b;
    const int tid = threadIdx.x;
    const int nbase = blockIdx.x * NPB;

    // ---- stage weights/biases ----
    {
        const float4* w1 = (const float4*)(W1 + layer * HID * HID);
        const float4* w2 = (const float4*)(W2 + layer * HID * HID);
        for (int idx = tid; idx < 1024; idx += 128) {
            int r = idx >> 4, c = idx & 15;
            *(float4*)&sm[OFF_W1 + r * WPAD + c * 4] = w1[idx];
            *(float4*)&sm[OFF_W2 + r * WPAD + c * 4] = w2[idx];
        }
        if (tid < HID) {
            sm[OFF_B1 + tid] = b1[layer * HID + tid];
            sm[OFF_B2 + tid] = b2[layer * HID + tid];
        }
    }

    // ---- stage z transposed (non-duplicated): sz[k][node] ----
    {
        int n = nbase + tid;
        float v[64];
        if (n < N_NODES) {
            const float4* zr = (const float4*)(g_z + n * HID);
#pragma unroll
            for (int q = 0; q < 16; q++) {
                float4 t4 = zr[q];
                v[4 * q + 0] = t4.x; v[4 * q + 1] = t4.y;
                v[4 * q + 2] = t4.z; v[4 * q + 3] = t4.w;
            }
        } else {
#pragma unroll
            for (int q = 0; q < 64; q++) v[q] = 0.f;
        }
#pragma unroll
        for (int k = 0; k < 64; k++) sm[OFF_Z + k * ZPAD + tid] = v[k];
    }
    __syncthreads();

    const int jg = tid & 7;          // col group: cols j0..j0+7
    const int ig = tid >> 3;         // node group: nodes i0..i0+7
    const int j0 = jg * 8;
    const int i0 = ig * 8;
    const unsigned zb = su32(sm + OFF_Z);

    unsigned long long acc[4][8];

    // ================= GEMV 1: y = relu(z @ W1 + b1) =================
    {
#pragma unroll
        for (int j = 0; j < 8; j++) {
            unsigned long long bd = dupf(sm[OFF_B1 + j0 + j]);
            acc[0][j] = bd; acc[1][j] = bd; acc[2][j] = bd; acc[3][j] = bd;
        }
        unsigned za = zb + i0 * 4;
#pragma unroll 4
        for (int k = 0; k < 64; k++) {
            unsigned long long z0, z1, z2, z3;
            asm("ld.shared.v2.u64 {%0,%1},[%2];" : "=l"(z0), "=l"(z1) : "r"(za));
            asm("ld.shared.v2.u64 {%0,%1},[%2];" : "=l"(z2), "=l"(z3) : "r"(za + 16));
#pragma unroll
            for (int j = 0; j < 8; j++) {
                unsigned long long wd = dupf(sm[OFF_W1 + k * WPAD + j0 + j]);
                FMA2(acc[0][j], z0, wd);
                FMA2(acc[1][j], z1, wd);
                FMA2(acc[2][j], z2, wd);
                FMA2(acc[3][j], z3, wd);
            }
            za += ZPAD * 4;
        }
    }
    __syncthreads();  // all z reads done before overwriting with y

    // relu + store y transposed (natural node pairs)
    {
#pragma unroll
        for (int p = 0; p < 4; p++) {
#pragma unroll
            for (int j = 0; j < 8; j++) {
                float lo, hi;
                asm("mov.b64 {%0,%1},%2;" : "=f"(lo), "=f"(hi) : "l"(acc[p][j]));
                lo = fmaxf(lo, 0.f);
                hi = fmaxf(hi, 0.f);
                unsigned ya = zb + (unsigned)((j0 + j) * ZPAD + i0 + 2 * p) * 4;
                asm volatile("st.shared.v2.b32 [%0],{%1,%2};"
                             :: "r"(ya), "f"(lo), "f"(hi));
            }
        }
    }
    __syncthreads();

    // ================= GEMV 2: hout = y @ W2 + b2 =================
    {
#pragma unroll
        for (int j = 0; j < 8; j++) {
            unsigned long long bd = dupf(sm[OFF_B2 + j0 + j]);
            acc[0][j] = bd; acc[1][j] = bd; acc[2][j] = bd; acc[3][j] = bd;
        }
        unsigned za = zb + i0 * 4;
#pragma unroll 4
        for (int k = 0; k < 64; k++) {
            unsigned long long z0, z1, z2, z3;
            asm("ld.shared.v2.u64 {%0,%1},[%2];" : "=l"(z0), "=l"(z1) : "r"(za));
            asm("ld.shared.v2.u64 {%0,%1},[%2];" : "=l"(z2), "=l"(z3) : "r"(za + 16));
#pragma unroll
            for (int j = 0; j < 8; j++) {
                unsigned long long wd = dupf(sm[OFF_W2 + k * WPAD + j0 + j]);
                FMA2(acc[0][j], z0, wd);
                FMA2(acc[1][j], z1, wd);
                FMA2(acc[2][j], z2, wd);
                FMA2(acc[3][j], z3, wd);
            }
            za += ZPAD * 4;
        }
    }

    if (!last) {
#pragma unroll
        for (int p = 0; p < 4; p++) {
            int n0 = nbase + i0 + 2 * p;
            float lo[8], hi[8];
#pragma unroll
            for (int j = 0; j < 8; j++)
                asm("mov.b64 {%0,%1},%2;" : "=f"(lo[j]), "=f"(hi[j]) : "l"(acc[p][j]));
            if (n0 < N_NODES) {
                float* pn = hout + n0 * HID + j0;
                *(float4*)(pn)     = make_float4(lo[0], lo[1], lo[2], lo[3]);
                *(float4*)(pn + 4) = make_float4(lo[4], lo[5], lo[6], lo[7]);
            }
            if (n0 + 1 < N_NODES) {
                float* pn = hout + (n0 + 1) * HID + j0;
                *(float4*)(pn)     = make_float4(hi[0], hi[1], hi[2], hi[3]);
                *(float4*)(pn + 4) = make_float4(hi[4], hi[5], hi[6], hi[7]);
            }
        }
    } else {
        // fused pool + head: partial dot over this thread's 8 cols, 8 nodes
        float dot[8];
#pragma unroll
        for (int a = 0; a < 8; a++) dot[a] = 0.f;
#pragma unroll
        for (int j = 0; j < 8; j++) {
            float wr = __ldg(Wr + j0 + j);
#pragma unroll
            for (int p = 0; p < 4; p++) {
                float lo, hi;
                asm("mov.b64 {%0,%1},%2;" : "=f"(lo), "=f"(hi) : "l"(acc[p][j]));
                dot[2 * p]     = fmaf(lo, wr, dot[2 * p]);
                dot[2 * p + 1] = fmaf(hi, wr, dot[2 * p + 1]);
            }
        }
        // reduce across the 8 jg lanes (same ig group within warp)
#pragma unroll
        for (int m = 1; m < 8; m <<= 1) {
#pragma unroll
            for (int a = 0; a < 8; a++)
                dot[a] += __shfl_xor_sync(0xffffffffu, dot[a], m);
        }
        if (jg == 0) {
#pragma unroll
            for (int a = 0; a < 8; a++) {
                int n = nbase + i0 + a;
                if (n < N_NODES)
                    atomicAdd(out + __ldg(gids + n), dot[a]);
            }
        }
    }
}

// ---------------------------------------------------------------------------
extern "C" void kernel_launch(void* const* d_in, const int* in_sizes, int n_in,
                              void* d_out, int out_size) {
    const int*   feats = (const int*)d_in[0];
    const int*   src   = (const int*)d_in[1];
    const int*   dst   = (const int*)d_in[2];
    const int*   gids  = (const int*)d_in[3];
    const float* emb   = (const float*)d_in[4];
    const float* W1    = (const float*)d_in[5];
    const float* b1    = (const float*)d_in[6];
    const float* W2    = (const float*)d_in[7];
    const float* b2    = (const float*)d_in[8];
    const float* Wr    = (const float*)d_in[9];
    float* out = (float*)d_out;

    cudaFuncSetAttribute(mlp_kernel,
                         cudaFuncAttributeMaxDynamicSharedMemorySize, SMEM_BYTES);

    // CSR build (padded rows) + prep
    void* deg_ptr = nullptr;
    cudaGetSymbolAddress(&deg_ptr, g_deg);
    cudaMemsetAsync(deg_ptr, 0, N_NODES * sizeof(int));
    cudaMemsetAsync(out, 0, N_GRAPHS * sizeof(float));
    fill_kernel<<<(CSR_CAP / 4 + 255) / 256, 256>>>();
    hist_kernel<<<(N_EDGES / 4 + 255) / 256, 256>>>(dst);
    prep_kernel<<<(N_NODES + 1 + 255) / 256, 256>>>(feats, emb);
    scan1_kernel<<<SCAN_BLKS, 1024>>>();
    scan2_kernel<<<1, 32>>>();
    scan3_kernel<<<(N_NODES + 255) / 256, 256>>>();
    scatter_kernel<<<(N_EDGES / 4 + 255) / 256, 256>>>(src, dst);

    // 3 GIN layers
    const int ablk = (N_NODES * 16 + 255) / 256;
    const int mblk = (N_NODES + NPB - 1) / NPB;

    agg0_kernel<<<ablk, 256>>>();
    mlp_kernel<<<mblk, 128, SMEM_BYTES>>>(W1, b1, W2, b2, 0, 0, gids, Wr, out);
    agg_kernel<<<ablk, 256>>>(1);
    mlp_kernel<<<mblk, 128, SMEM_BYTES>>>(W1, b1, W2, b2, 1, 0, gids, Wr, out);
    agg_kernel<<<ablk, 256>>>(2);
    mlp_kernel<<<mblk, 128, SMEM_BYTES>>>(W1, b1, W2, b2, 2, 1, gids, Wr, out);
}

// round 8
// speedup vs baseline: 1.6521x; 1.0457x over previous
#include <cuda_runtime.h>
#include <cuda_fp16.h>

#define N_NODES  50000
#define N_EDGES  800000
#define N_GRAPHS 128
#define HID      64
#define VOCAB    100
#define LAYERS   3
#define NPB      128                          // nodes per block in mlp kernel
#define CSR_CAP  (N_EDGES + 7 * N_NODES)      // padded CSR capacity
#define SCAN_BLKS ((N_NODES + 1023) / 1024)   // 49

// Scratch (__device__ globals — allocation-free rule).
// Row N_NODES of g_hh is a permanent ZERO row (never written): padded-CSR
// dummy gather target. Row VOCAB of g_emb_pad likewise.
__device__ __half g_hh[(N_NODES + 1) * HID];   // fp16 inter-layer h (128B/row)
__device__ float  g_z[N_NODES * HID];
__device__ float  g_emb_pad[(VOCAB + 1) * HID];
__device__ int    g_feats_pad[N_NODES + 1];
__device__ int    g_deg[N_NODES];
__device__ int    g_rowptr[N_NODES + 1];
__device__ int    g_pos[N_NODES];
__device__ int    g_bsum[SCAN_BLKS];
__device__ int    g_boff[SCAN_BLKS];
__device__ int    g_csr_src[CSR_CAP];

// ---------------------------------------------------------------------------
// Setup: CSR fill + degree histogram + padded emb/feats (one kernel)
// ---------------------------------------------------------------------------
__global__ void setup_kernel(const int* __restrict__ dst,
                             const int* __restrict__ feats,
                             const float* __restrict__ emb) {
    int i = blockIdx.x * blockDim.x + threadIdx.x;
    if (i * 4 < CSR_CAP)
        ((int4*)g_csr_src)[i] = make_int4(N_NODES, N_NODES, N_NODES, N_NODES);
    if (i * 4 < N_EDGES) {
        int4 d = ((const int4*)dst)[i];
        atomicAdd(&g_deg[d.x], 1);
        atomicAdd(&g_deg[d.y], 1);
        atomicAdd(&g_deg[d.z], 1);
        atomicAdd(&g_deg[d.w], 1);
    }
    if (i < (VOCAB + 1) * HID)
        g_emb_pad[i] = (i < VOCAB * HID) ? emb[i] : 0.f;
    if (i < N_NODES)       g_feats_pad[i] = __ldg(feats + i);
    else if (i == N_NODES) g_feats_pad[i] = VOCAB;
}

// Phase 1: per-block Hillis-Steele scan of PADDED degrees (1024 nodes/block).
__global__ void __launch_bounds__(1024) scan1_kernel() {
    __shared__ int ssum[1024];
    int t = threadIdx.x;
    int i = blockIdx.x * 1024 + t;
    int d = (i < N_NODES) ? ((g_deg[i] + 7) & ~7) : 0;
    ssum[t] = d;
    __syncthreads();
    for (int off = 1; off < 1024; off <<= 1) {
        int v = (t >= off) ? ssum[t - off] : 0;
        __syncthreads();
        ssum[t] += v;
        __syncthreads();
    }
    if (i < N_NODES) g_rowptr[i] = ssum[t] - d;
    if (t == 1023) g_bsum[blockIdx.x] = ssum[1023];
}

// Phase 2: one warp scans the 49 block sums.
__global__ void scan2_kernel() {
    int t = threadIdx.x;
    int i0 = 2 * t, i1 = 2 * t + 1;
    int v0 = (i0 < SCAN_BLKS) ? g_bsum[i0] : 0;
    int v1 = (i1 < SCAN_BLKS) ? g_bsum[i1] : 0;
    int s = v0 + v1;
    int incl = s;
#pragma unroll
    for (int off = 1; off < 32; off <<= 1) {
        int u = __shfl_up_sync(0xffffffffu, incl, off);
        if (t >= off) incl += u;
    }
    int excl = incl - s;
    if (i0 < SCAN_BLKS) g_boff[i0] = excl;
    if (i1 < SCAN_BLKS) g_boff[i1] = excl + v0;
    if (t == 31) g_rowptr[N_NODES] = incl;
}

// Phase 3: add block offsets, copy to g_pos.
__global__ void scan3_kernel() {
    int i = blockIdx.x * blockDim.x + threadIdx.x;
    if (i >= N_NODES) return;
    int r = g_rowptr[i] + g_boff[i >> 10];
    g_rowptr[i] = r;
    g_pos[i]    = r;
}

__global__ void scatter_kernel(const int* __restrict__ src,
                               const int* __restrict__ dst) {
    int i = blockIdx.x * blockDim.x + threadIdx.x;
    if (i * 4 >= N_EDGES) return;
    int4 s = ((const int4*)src)[i];
    int4 d = ((const int4*)dst)[i];
    int p;
    p = atomicAdd(&g_pos[d.x], 1); g_csr_src[p] = s.x;
    p = atomicAdd(&g_pos[d.y], 1); g_csr_src[p] = s.y;
    p = atomicAdd(&g_pos[d.z], 1); g_csr_src[p] = s.z;
    p = atomicAdd(&g_pos[d.w], 1); g_csr_src[p] = s.w;
}

// ---------------------------------------------------------------------------
// Layer-0 aggregation from the (L1-resident, 25KB) fp32 embedding table:
// z[n] = emb[f[n]] + sum_{s in N(n)} emb[f[s]].   (exact fp32)
// ---------------------------------------------------------------------------
__global__ void __launch_bounds__(256)
agg0_kernel() {
    int i = blockIdx.x * blockDim.x + threadIdx.x;
    if (i >= N_NODES * 16) return;
    int n = i >> 4;
    int c = i & 15;
    const float4* e4 = (const float4*)g_emb_pad;

    float4 acc = e4[__ldg(&g_feats_pad[n]) * 16 + c];
    int e   = __ldg(&g_rowptr[n]);
    int end = __ldg(&g_rowptr[n + 1]);

    for (; e < end; e += 8) {
        int4 sa = *(const int4*)&g_csr_src[e];
        int4 sb = *(const int4*)&g_csr_src[e + 4];
        int f0 = __ldg(&g_feats_pad[sa.x]);
        int f1 = __ldg(&g_feats_pad[sa.y]);
        int f2 = __ldg(&g_feats_pad[sa.z]);
        int f3 = __ldg(&g_feats_pad[sa.w]);
        int f4 = __ldg(&g_feats_pad[sb.x]);
        int f5 = __ldg(&g_feats_pad[sb.y]);
        int f6 = __ldg(&g_feats_pad[sb.z]);
        int f7 = __ldg(&g_feats_pad[sb.w]);
        float4 v0 = e4[f0 * 16 + c];
        float4 v1 = e4[f1 * 16 + c];
        float4 v2 = e4[f2 * 16 + c];
        float4 v3 = e4[f3 * 16 + c];
        float4 v4 = e4[f4 * 16 + c];
        float4 v5 = e4[f5 * 16 + c];
        float4 v6 = e4[f6 * 16 + c];
        float4 v7 = e4[f7 * 16 + c];
        acc.x += v0.x; acc.y += v0.y; acc.z += v0.z; acc.w += v0.w;
        acc.x += v1.x; acc.y += v1.y; acc.z += v1.z; acc.w += v1.w;
        acc.x += v2.x; acc.y += v2.y; acc.z += v2.z; acc.w += v2.w;
        acc.x += v3.x; acc.y += v3.y; acc.z += v3.z; acc.w += v3.w;
        acc.x += v4.x; acc.y += v4.y; acc.z += v4.z; acc.w += v4.w;
        acc.x += v5.x; acc.y += v5.y; acc.z += v5.z; acc.w += v5.w;
        acc.x += v6.x; acc.y += v6.y; acc.z += v6.z; acc.w += v6.w;
        acc.x += v7.x; acc.y += v7.y; acc.z += v7.z; acc.w += v7.w;
    }
    ((float4*)g_z)[n * 16 + c] = acc;
}

// ---------------------------------------------------------------------------
// Layers 1,2 aggregation (fp16 h, 128B/node row):
// z[n] = h[n] + sum_{s in N(n)} h[s], accumulated in fp32.
// 8 threads per node, each owns one uint4 (8 halves). Padded CSR, 8-deep.
// ---------------------------------------------------------------------------
__device__ __forceinline__ void acc8h(float4& A, float4& B, uint4 u) {
    float2 f;
    f = __half22float2(*(const __half2*)&u.x); A.x += f.x; A.y += f.y;
    f = __half22float2(*(const __half2*)&u.y); A.z += f.x; A.w += f.y;
    f = __half22float2(*(const __half2*)&u.z); B.x += f.x; B.y += f.y;
    f = __half22float2(*(const __half2*)&u.w); B.z += f.x; B.w += f.y;
}

__global__ void __launch_bounds__(256)
agg_kernel() {
    int i = blockIdx.x * blockDim.x + threadIdx.x;
    if (i >= N_NODES * 8) return;
    int n = i >> 3;
    int c = i & 7;
    const uint4* hh = (const uint4*)g_hh;

    float4 A = {0.f, 0.f, 0.f, 0.f}, B = {0.f, 0.f, 0.f, 0.f};
    acc8h(A, B, hh[n * 8 + c]);          // self term

    int e   = __ldg(&g_rowptr[n]);
    int end = __ldg(&g_rowptr[n + 1]);
    for (; e < end; e += 8) {
        int4 sa = *(const int4*)&g_csr_src[e];
        int4 sb = *(const int4*)&g_csr_src[e + 4];
        uint4 u0 = hh[sa.x * 8 + c];
        uint4 u1 = hh[sa.y * 8 + c];
        uint4 u2 = hh[sa.z * 8 + c];
        uint4 u3 = hh[sa.w * 8 + c];
        uint4 u4 = hh[sb.x * 8 + c];
        uint4 u5 = hh[sb.y * 8 + c];
        uint4 u6 = hh[sb.z * 8 + c];
        uint4 u7 = hh[sb.w * 8 + c];
        acc8h(A, B, u0);
        acc8h(A, B, u1);
        acc8h(A, B, u2);
        acc8h(A, B, u3);
        acc8h(A, B, u4);
        acc8h(A, B, u5);
        acc8h(A, B, u6);
        acc8h(A, B, u7);
    }
    ((float4*)g_z)[n * 16 + 2 * c]     = A;
    ((float4*)g_z)[n * 16 + 2 * c + 1] = B;
}

// ---------------------------------------------------------------------------
// MLP: h = relu(z@W1+b1)@W2 + b2, stored as fp16 (128B/node).
// 128 threads, 128 nodes/block. Thread = 8 nodes x 8 cols (node-paired fma2).
// LAST layer: fused pool+head instead of the h store.
// ---------------------------------------------------------------------------
#define OFF_W1 0
#define OFF_W2 4352
#define OFF_B1 8704
#define OFF_B2 8768
#define OFF_Z  8832
#define WPAD   68
#define ZPAD   132
#define SMEM_BYTES (17280 * 4)

__device__ __forceinline__ unsigned su32(const void* p) {
    return (unsigned)__cvta_generic_to_shared(p);
}
__device__ __forceinline__ unsigned long long dupf(float x) {
    unsigned long long r;
    asm("mov.b64 %0, {%1, %1};" : "=l"(r) : "f"(x));
    return r;
}
#define FMA2(d, a, b) asm("fma.rn.f32x2 %0, %1, %2, %0;" : "+l"(d) : "l"(a), "l"(b))

__global__ void __launch_bounds__(128)
mlp_kernel(const float* __restrict__ W1, const float* __restrict__ b1,
           const float* __restrict__ W2, const float* __restrict__ b2,
           int layer, int last,
           const int* __restrict__ gids, const float* __restrict__ Wr,
           float* __restrict__ out) {
    extern __shared__ __align__(16) float sm[];
    const int tid = threadIdx.x;
    const int nbase = blockIdx.x * NPB;

    // ---- stage weights/biases ----
    {
        const float4* w1 = (const float4*)(W1 + layer * HID * HID);
        const float4* w2 = (const float4*)(W2 + layer * HID * HID);
        for (int idx = tid; idx < 1024; idx += 128) {
            int r = idx >> 4, c = idx & 15;
            *(float4*)&sm[OFF_W1 + r * WPAD + c * 4] = w1[idx];
            *(float4*)&sm[OFF_W2 + r * WPAD + c * 4] = w2[idx];
        }
        if (tid < HID) {
            sm[OFF_B1 + tid] = b1[layer * HID + tid];
            sm[OFF_B2 + tid] = b2[layer * HID + tid];
        }
    }

    // ---- stage z transposed: sz[k][node] ----
    {
        int n = nbase + tid;
        float v[64];
        if (n < N_NODES) {
            const float4* zr = (const float4*)(g_z + n * HID);
#pragma unroll
            for (int q = 0; q < 16; q++) {
                float4 t4 = zr[q];
                v[4 * q + 0] = t4.x; v[4 * q + 1] = t4.y;
                v[4 * q + 2] = t4.z; v[4 * q + 3] = t4.w;
            }
        } else {
#pragma unroll
            for (int q = 0; q < 64; q++) v[q] = 0.f;
        }
#pragma unroll
        for (int k = 0; k < 64; k++) sm[OFF_Z + k * ZPAD + tid] = v[k];
    }
    __syncthreads();

    const int jg = tid & 7;          // col group: cols j0..j0+7
    const int ig = tid >> 3;         // node group: nodes i0..i0+7
    const int j0 = jg * 8;
    const int i0 = ig * 8;
    const unsigned zb = su32(sm + OFF_Z);

    unsigned long long acc[4][8];

    // ================= GEMV 1: y = relu(z @ W1 + b1) =================
    {
#pragma unroll
        for (int j = 0; j < 8; j++) {
            unsigned long long bd = dupf(sm[OFF_B1 + j0 + j]);
            acc[0][j] = bd; acc[1][j] = bd; acc[2][j] = bd; acc[3][j] = bd;
        }
        unsigned za = zb + i0 * 4;
#pragma unroll 4
        for (int k = 0; k < 64; k++) {
            unsigned long long z0, z1, z2, z3;
            asm("ld.shared.v2.u64 {%0,%1},[%2];" : "=l"(z0), "=l"(z1) : "r"(za));
            asm("ld.shared.v2.u64 {%0,%1},[%2];" : "=l"(z2), "=l"(z3) : "r"(za + 16));
#pragma unroll
            for (int j = 0; j < 8; j++) {
                unsigned long long wd = dupf(sm[OFF_W1 + k * WPAD + j0 + j]);
                FMA2(acc[0][j], z0, wd);
                FMA2(acc[1][j], z1, wd);
                FMA2(acc[2][j], z2, wd);
                FMA2(acc[3][j], z3, wd);
            }
            za += ZPAD * 4;
        }
    }
    __syncthreads();

    // relu + store y transposed
    {
#pragma unroll
        for (int p = 0; p < 4; p++) {
#pragma unroll
            for (int j = 0; j < 8; j++) {
                float lo, hi;
                asm("mov.b64 {%0,%1},%2;" : "=f"(lo), "=f"(hi) : "l"(acc[p][j]));
                lo = fmaxf(lo, 0.f);
                hi = fmaxf(hi, 0.f);
                unsigned ya = zb + (unsigned)((j0 + j) * ZPAD + i0 + 2 * p) * 4;
                asm volatile("st.shared.v2.b32 [%0],{%1,%2};"
                             :: "r"(ya), "f"(lo), "f"(hi));
            }
        }
    }
    __syncthreads();

    // ================= GEMV 2: h = y @ W2 + b2 =================
    {
#pragma unroll
        for (int j = 0; j < 8; j++) {
            unsigned long long bd = dupf(sm[OFF_B2 + j0 + j]);
            acc[0][j] = bd; acc[1][j] = bd; acc[2][j] = bd; acc[3][j] = bd;
        }
        unsigned za = zb + i0 * 4;
#pragma unroll 4
        for (int k = 0; k < 64; k++) {
            unsigned long long z0, z1, z2, z3;
            asm("ld.shared.v2.u64 {%0,%1},[%2];" : "=l"(z0), "=l"(z1) : "r"(za));
            asm("ld.shared.v2.u64 {%0,%1},[%2];" : "=l"(z2), "=l"(z3) : "r"(za + 16));
#pragma unroll
            for (int j = 0; j < 8; j++) {
                unsigned long long wd = dupf(sm[OFF_W2 + k * WPAD + j0 + j]);
                FMA2(acc[0][j], z0, wd);
                FMA2(acc[1][j], z1, wd);
                FMA2(acc[2][j], z2, wd);
                FMA2(acc[3][j], z3, wd);
            }
            za += ZPAD * 4;
        }
    }

    if (!last) {
        // store h as fp16 (one 16B vector per node per thread)
#pragma unroll
        for (int p = 0; p < 4; p++) {
            int n0 = nbase + i0 + 2 * p;
            float lo[8], hi[8];
#pragma unroll
            for (int j = 0; j < 8; j++)
                asm("mov.b64 {%0,%1},%2;" : "=f"(lo[j]), "=f"(hi[j]) : "l"(acc[p][j]));
            if (n0 < N_NODES) {
                __half2 q0 = __floats2half2_rn(lo[0], lo[1]);
                __half2 q1 = __floats2half2_rn(lo[2], lo[3]);
                __half2 q2 = __floats2half2_rn(lo[4], lo[5]);
                __half2 q3 = __floats2half2_rn(lo[6], lo[7]);
                uint4 v = make_uint4(*(unsigned*)&q0, *(unsigned*)&q1,
                                     *(unsigned*)&q2, *(unsigned*)&q3);
                *(uint4*)(g_hh + n0 * HID + j0) = v;
            }
            if (n0 + 1 < N_NODES) {
                __half2 q0 = __floats2half2_rn(hi[0], hi[1]);
                __half2 q1 = __floats2half2_rn(hi[2], hi[3]);
                __half2 q2 = __floats2half2_rn(hi[4], hi[5]);
                __half2 q3 = __floats2half2_rn(hi[6], hi[7]);
                uint4 v = make_uint4(*(unsigned*)&q0, *(unsigned*)&q1,
                                     *(unsigned*)&q2, *(unsigned*)&q3);
                *(uint4*)(g_hh + (n0 + 1) * HID + j0) = v;
            }
        }
    } else {
        // fused pool + head
        float dot[8];
#pragma unroll
        for (int a = 0; a < 8; a++) dot[a] = 0.f;
#pragma unroll
        for (int j = 0; j < 8; j++) {
            float wr = __ldg(Wr + j0 + j);
#pragma unroll
            for (int p = 0; p < 4; p++) {
                float lo, hi;
                asm("mov.b64 {%0,%1},%2;" : "=f"(lo), "=f"(hi) : "l"(acc[p][j]));
                dot[2 * p]     = fmaf(lo, wr, dot[2 * p]);
                dot[2 * p + 1] = fmaf(hi, wr, dot[2 * p + 1]);
            }
        }
#pragma unroll
        for (int m = 1; m < 8; m <<= 1) {
#pragma unroll
            for (int a = 0; a < 8; a++)
                dot[a] += __shfl_xor_sync(0xffffffffu, dot[a], m);
        }
        if (jg == 0) {
#pragma unroll
            for (int a = 0; a < 8; a++) {
                int n = nbase + i0 + a;
                if (n < N_NODES)
                    atomicAdd(out + __ldg(gids + n), dot[a]);
            }
        }
    }
}

// ---------------------------------------------------------------------------
extern "C" void kernel_launch(void* const* d_in, const int* in_sizes, int n_in,
                              void* d_out, int out_size) {
    const int*   feats = (const int*)d_in[0];
    const int*   src   = (const int*)d_in[1];
    const int*   dst   = (const int*)d_in[2];
    const int*   gids  = (const int*)d_in[3];
    const float* emb   = (const float*)d_in[4];
    const float* W1    = (const float*)d_in[5];
    const float* b1    = (const float*)d_in[6];
    const float* W2    = (const float*)d_in[7];
    const float* b2    = (const float*)d_in[8];
    const float* Wr    = (const float*)d_in[9];
    float* out = (float*)d_out;

    cudaFuncSetAttribute(mlp_kernel,
                         cudaFuncAttributeMaxDynamicSharedMemorySize, SMEM_BYTES);

    // CSR build (padded rows) + prep
    void* deg_ptr = nullptr;
    cudaGetSymbolAddress(&deg_ptr, g_deg);
    cudaMemsetAsync(deg_ptr, 0, N_NODES * sizeof(int));
    cudaMemsetAsync(out, 0, N_GRAPHS * sizeof(float));
    setup_kernel<<<(CSR_CAP / 4 + 255) / 256, 256>>>(dst, feats, emb);
    scan1_kernel<<<SCAN_BLKS, 1024>>>();
    scan2_kernel<<<1, 32>>>();
    scan3_kernel<<<(N_NODES + 255) / 256, 256>>>();
    scatter_kernel<<<(N_EDGES / 4 + 255) / 256, 256>>>(src, dst);

    // 3 GIN layers
    const int a0blk = (N_NODES * 16 + 255) / 256;
    const int ablk  = (N_NODES * 8 + 255) / 256;
    const int mblk  = (N_NODES + NPB - 1) / NPB;

    agg0_kernel<<<a0blk, 256>>>();
    mlp_kernel<<<mblk, 128, SMEM_BYTES>>>(W1, b1, W2, b2, 0, 0, gids, Wr, out);
    agg_kernel<<<ablk, 256>>>();
    mlp_kernel<<<mblk, 128, SMEM_BYTES>>>(W1, b1, W2, b2, 1, 0, gids, Wr, out);
    agg_kernel<<<ablk, 256>>>();
    mlp_kernel<<<mblk, 128, SMEM_BYTES>>>(W1, b1, W2, b2, 2, 1, gids, Wr, out);
}

// round 9
// speedup vs baseline: 1.7016x; 1.0299x over previous
#include <cuda_runtime.h>
#include <cuda_fp16.h>

#define N_NODES  50000
#define N_EDGES  800000
#define N_GRAPHS 128
#define HID      64
#define VOCAB    100
#define LAYERS   3
#define NPB      128                          // nodes per block in mlp kernel
#define CSR_CAP  (N_EDGES + 7 * N_NODES)      // padded CSR capacity
#define SCAN_BLKS ((N_NODES + 1023) / 1024)   // 49

// Scratch (__device__ globals — allocation-free rule).
// Row N_NODES of g_hh is a permanent ZERO row (never written): padded-CSR
// dummy gather target. Row VOCAB of g_emb_pad likewise.
// g_deg invariant: zero at entry to every call (static init; scan_kernel
// re-zeros it after reading). g_blk_agg zeroed by setup_kernel each call.
__device__ __half g_hh[(N_NODES + 1) * HID];   // fp16 inter-layer h (128B/row)
__device__ float  g_z[N_NODES * HID];
__device__ float  g_emb_pad[(VOCAB + 1) * HID];
__device__ int    g_feats_pad[N_NODES + 1];
__device__ int    g_deg[N_NODES];
__device__ int    g_rowptr[N_NODES + 1];
__device__ int    g_pos[N_NODES];
__device__ int    g_blk_agg[SCAN_BLKS];
__device__ int    g_csr_src[CSR_CAP];

// ---------------------------------------------------------------------------
// Setup: CSR pad-fill + degree histogram + padded emb/feats + zero out/agg
// ---------------------------------------------------------------------------
__global__ void setup_kernel(const int* __restrict__ dst,
                             const int* __restrict__ feats,
                             const float* __restrict__ emb,
                             float* __restrict__ out) {
    int i = blockIdx.x * blockDim.x + threadIdx.x;
    if (i * 4 < CSR_CAP)
        ((int4*)g_csr_src)[i] = make_int4(N_NODES, N_NODES, N_NODES, N_NODES);
    if (i * 4 < N_EDGES) {
        int4 d = ((const int4*)dst)[i];
        atomicAdd(&g_deg[d.x], 1);
        atomicAdd(&g_deg[d.y], 1);
        atomicAdd(&g_deg[d.z], 1);
        atomicAdd(&g_deg[d.w], 1);
    }
    if (i < (VOCAB + 1) * HID)
        g_emb_pad[i] = (i < VOCAB * HID) ? emb[i] : 0.f;
    if (i < N_NODES)       g_feats_pad[i] = __ldg(feats + i);
    else if (i == N_NODES) g_feats_pad[i] = VOCAB;
    if (i < SCAN_BLKS) g_blk_agg[i] = 0;
    if (i < N_GRAPHS)  out[i] = 0.f;
}

// ---------------------------------------------------------------------------
// Single-pass scan of PADDED degrees (rounded up to x8) -> rowptr + pos.
// 49 blocks x 1024 threads: all resident in one wave (49 < 148 SMs), so
// spinning on predecessor aggregates cannot deadlock. Aggregate+flag share
// ONE 32-bit word (value+1; 0 = not ready) -> no fence needed.
// Also re-zeros g_deg (read-once-then-zero) for the next call.
// ---------------------------------------------------------------------------
__global__ void __launch_bounds__(1024) scan_kernel() {
    __shared__ int warp_sums[32];
    __shared__ int block_prefix;
    const int t = threadIdx.x, b = blockIdx.x;
    const int lane = t & 31, warp = t >> 5;
    if (t == 0) block_prefix = 0;

    int i = b * 1024 + t;
    int d = 0;
    if (i < N_NODES) {
        d = (g_deg[i] + 7) & ~7;
        g_deg[i] = 0;                      // re-zero for next call
    }

    // warp inclusive scan
    int incl = d;
#pragma unroll
    for (int off = 1; off < 32; off <<= 1) {
        int u = __shfl_up_sync(0xffffffffu, incl, off);
        if (lane >= off) incl += u;
    }
    if (lane == 31) warp_sums[warp] = incl;
    __syncthreads();

    // warp 0 scans the 32 warp sums
    if (warp == 0) {
        int v = warp_sums[lane];
        int w = v;
#pragma unroll
        for (int off = 1; off < 32; off <<= 1) {
            int u = __shfl_up_sync(0xffffffffu, w, off);
            if (lane >= off) w += u;
        }
        warp_sums[lane] = w;
    }
    __syncthreads();

    int wexcl = (warp > 0) ? warp_sums[warp - 1] : 0;
    int excl  = wexcl + incl - d;          // exclusive prefix within block
    int block_total = warp_sums[31];

    // publish own aggregate (single-word value+flag)
    if (t == 0)
        *(volatile int*)&g_blk_agg[b] = block_total + 1;

    // lookback: threads t < b each spin for one predecessor aggregate
    if (t < b) {
        int v;
        do { v = *(volatile int*)&g_blk_agg[t]; } while (v == 0);
        atomicAdd(&block_prefix, v - 1);
    }
    __syncthreads();

    int r = block_prefix + excl;
    if (i < N_NODES) {
        g_rowptr[i] = r;
        g_pos[i]    = r;
    }
    if (b == SCAN_BLKS - 1 && t == 1023)
        g_rowptr[N_NODES] = block_prefix + excl + d;
}

__global__ void scatter_kernel(const int* __restrict__ src,
                               const int* __restrict__ dst) {
    int i = blockIdx.x * blockDim.x + threadIdx.x;
    if (i * 4 >= N_EDGES) return;
    int4 s = ((const int4*)src)[i];
    int4 d = ((const int4*)dst)[i];
    int p;
    p = atomicAdd(&g_pos[d.x], 1); g_csr_src[p] = s.x;
    p = atomicAdd(&g_pos[d.y], 1); g_csr_src[p] = s.y;
    p = atomicAdd(&g_pos[d.z], 1); g_csr_src[p] = s.z;
    p = atomicAdd(&g_pos[d.w], 1); g_csr_src[p] = s.w;
}

// ---------------------------------------------------------------------------
// Layer-0 aggregation from the (L1-resident, 25KB) fp32 embedding table:
// z[n] = emb[f[n]] + sum_{s in N(n)} emb[f[s]].   (exact fp32)
// ---------------------------------------------------------------------------
__global__ void __launch_bounds__(256)
agg0_kernel() {
    int i = blockIdx.x * blockDim.x + threadIdx.x;
    if (i >= N_NODES * 16) return;
    int n = i >> 4;
    int c = i & 15;
    const float4* e4 = (const float4*)g_emb_pad;

    float4 acc = e4[__ldg(&g_feats_pad[n]) * 16 + c];
    int e   = __ldg(&g_rowptr[n]);
    int end = __ldg(&g_rowptr[n + 1]);

    for (; e < end; e += 8) {
        int4 sa = *(const int4*)&g_csr_src[e];
        int4 sb = *(const int4*)&g_csr_src[e + 4];
        int f0 = __ldg(&g_feats_pad[sa.x]);
        int f1 = __ldg(&g_feats_pad[sa.y]);
        int f2 = __ldg(&g_feats_pad[sa.z]);
        int f3 = __ldg(&g_feats_pad[sa.w]);
        int f4 = __ldg(&g_feats_pad[sb.x]);
        int f5 = __ldg(&g_feats_pad[sb.y]);
        int f6 = __ldg(&g_feats_pad[sb.z]);
        int f7 = __ldg(&g_feats_pad[sb.w]);
        float4 v0 = e4[f0 * 16 + c];
        float4 v1 = e4[f1 * 16 + c];
        float4 v2 = e4[f2 * 16 + c];
        float4 v3 = e4[f3 * 16 + c];
        float4 v4 = e4[f4 * 16 + c];
        float4 v5 = e4[f5 * 16 + c];
        float4 v6 = e4[f6 * 16 + c];
        float4 v7 = e4[f7 * 16 + c];
        acc.x += v0.x; acc.y += v0.y; acc.z += v0.z; acc.w += v0.w;
        acc.x += v1.x; acc.y += v1.y; acc.z += v1.z; acc.w += v1.w;
        acc.x += v2.x; acc.y += v2.y; acc.z += v2.z; acc.w += v2.w;
        acc.x += v3.x; acc.y += v3.y; acc.z += v3.z; acc.w += v3.w;
        acc.x += v4.x; acc.y += v4.y; acc.z += v4.z; acc.w += v4.w;
        acc.x += v5.x; acc.y += v5.y; acc.z += v5.z; acc.w += v5.w;
        acc.x += v6.x; acc.y += v6.y; acc.z += v6.z; acc.w += v6.w;
        acc.x += v7.x; acc.y += v7.y; acc.z += v7.z; acc.w += v7.w;
    }
    ((float4*)g_z)[n * 16 + c] = acc;
}

// ---------------------------------------------------------------------------
// Layers 1,2 aggregation (fp16 h, 128B/node row):
// z[n] = h[n] + sum_{s in N(n)} h[s], accumulated in fp32.
// 8 threads per node, each owns one uint4 (8 halves). Padded CSR, 8-deep.
// ---------------------------------------------------------------------------
__device__ __forceinline__ void acc8h(float4& A, float4& B, uint4 u) {
    float2 f;
    f = __half22float2(*(const __half2*)&u.x); A.x += f.x; A.y += f.y;
    f = __half22float2(*(const __half2*)&u.y); A.z += f.x; A.w += f.y;
    f = __half22float2(*(const __half2*)&u.z); B.x += f.x; B.y += f.y;
    f = __half22float2(*(const __half2*)&u.w); B.z += f.x; B.w += f.y;
}

__global__ void __launch_bounds__(256)
agg_kernel() {
    int i = blockIdx.x * blockDim.x + threadIdx.x;
    if (i >= N_NODES * 8) return;
    int n = i >> 3;
    int c = i & 7;
    const uint4* hh = (const uint4*)g_hh;

    float4 A = {0.f, 0.f, 0.f, 0.f}, B = {0.f, 0.f, 0.f, 0.f};
    acc8h(A, B, hh[n * 8 + c]);          // self term

    int e   = __ldg(&g_rowptr[n]);
    int end = __ldg(&g_rowptr[n + 1]);
    for (; e < end; e += 8) {
        int4 sa = *(const int4*)&g_csr_src[e];
        int4 sb = *(const int4*)&g_csr_src[e + 4];
        uint4 u0 = hh[sa.x * 8 + c];
        uint4 u1 = hh[sa.y * 8 + c];
        uint4 u2 = hh[sa.z * 8 + c];
        uint4 u3 = hh[sa.w * 8 + c];
        uint4 u4 = hh[sb.x * 8 + c];
        uint4 u5 = hh[sb.y * 8 + c];
        uint4 u6 = hh[sb.z * 8 + c];
        uint4 u7 = hh[sb.w * 8 + c];
        acc8h(A, B, u0);
        acc8h(A, B, u1);
        acc8h(A, B, u2);
        acc8h(A, B, u3);
        acc8h(A, B, u4);
        acc8h(A, B, u5);
        acc8h(A, B, u6);
        acc8h(A, B, u7);
    }
    ((float4*)g_z)[n * 16 + 2 * c]     = A;
    ((float4*)g_z)[n * 16 + 2 * c + 1] = B;
}

// ---------------------------------------------------------------------------
// MLP: h = relu(z@W1+b1)@W2 + b2, stored as fp16 (128B/node).
// 128 threads, 128 nodes/block. Thread = 8 nodes x 8 cols (node-paired fma2).
// LAST layer: fused pool+head instead of the h store.
// ---------------------------------------------------------------------------
#define OFF_W1 0
#define OFF_W2 4352
#define OFF_B1 8704
#define OFF_B2 8768
#define OFF_Z  8832
#define WPAD   68
#define ZPAD   132
#define SMEM_BYTES (17280 * 4)

__device__ __forceinline__ unsigned su32(const void* p) {
    return (unsigned)__cvta_generic_to_shared(p);
}
__device__ __forceinline__ unsigned long long dupf(float x) {
    unsigned long long r;
    asm("mov.b64 %0, {%1, %1};" : "=l"(r) : "f"(x));
    return r;
}
#define FMA2(d, a, b) asm("fma.rn.f32x2 %0, %1, %2, %0;" : "+l"(d) : "l"(a), "l"(b))

__global__ void __launch_bounds__(128)
mlp_kernel(const float* __restrict__ W1, const float* __restrict__ b1,
           const float* __restrict__ W2, const float* __restrict__ b2,
           int layer, int last,
           const int* __restrict__ gids, const float* __restrict__ Wr,
           float* __restrict__ out) {
    extern __shared__ __align__(16) float sm[];
    const int tid = threadIdx.x;
    const int nbase = blockIdx.x * NPB;

    // ---- stage weights/biases ----
    {
        const float4* w1 = (const float4*)(W1 + layer * HID * HID);
        const float4* w2 = (const float4*)(W2 + layer * HID * HID);
        for (int idx = tid; idx < 1024; idx += 128) {
            int r = idx >> 4, c = idx & 15;
            *(float4*)&sm[OFF_W1 + r * WPAD + c * 4] = w1[idx];
            *(float4*)&sm[OFF_W2 + r * WPAD + c * 4] = w2[idx];
        }
        if (tid < HID) {
            sm[OFF_B1 + tid] = b1[layer * HID + tid];
            sm[OFF_B2 + tid] = b2[layer * HID + tid];
        }
    }

    // ---- stage z transposed: sz[k][node] ----
    {
        int n = nbase + tid;
        float v[64];
        if (n < N_NODES) {
            const float4* zr = (const float4*)(g_z + n * HID);
#pragma unroll
            for (int q = 0; q < 16; q++) {
                float4 t4 = zr[q];
                v[4 * q + 0] = t4.x; v[4 * q + 1] = t4.y;
                v[4 * q + 2] = t4.z; v[4 * q + 3] = t4.w;
            }
        } else {
#pragma unroll
            for (int q = 0; q < 64; q++) v[q] = 0.f;
        }
#pragma unroll
        for (int k = 0; k < 64; k++) sm[OFF_Z + k * ZPAD + tid] = v[k];
    }
    __syncthreads();

    const int jg = tid & 7;          // col group: cols j0..j0+7
    const int ig = tid >> 3;         // node group: nodes i0..i0+7
    const int j0 = jg * 8;
    const int i0 = ig * 8;
    const unsigned zb = su32(sm + OFF_Z);

    unsigned long long acc[4][8];

    // ================= GEMV 1: y = relu(z @ W1 + b1) =================
    {
#pragma unroll
        for (int j = 0; j < 8; j++) {
            unsigned long long bd = dupf(sm[OFF_B1 + j0 + j]);
            acc[0][j] = bd; acc[1][j] = bd; acc[2][j] = bd; acc[3][j] = bd;
        }
        unsigned za = zb + i0 * 4;
#pragma unroll 4
        for (int k = 0; k < 64; k++) {
            unsigned long long z0, z1, z2, z3;
            asm("ld.shared.v2.u64 {%0,%1},[%2];" : "=l"(z0), "=l"(z1) : "r"(za));
            asm("ld.shared.v2.u64 {%0,%1},[%2];" : "=l"(z2), "=l"(z3) : "r"(za + 16));
#pragma unroll
            for (int j = 0; j < 8; j++) {
                unsigned long long wd = dupf(sm[OFF_W1 + k * WPAD + j0 + j]);
                FMA2(acc[0][j], z0, wd);
                FMA2(acc[1][j], z1, wd);
                FMA2(acc[2][j], z2, wd);
                FMA2(acc[3][j], z3, wd);
            }
            za += ZPAD * 4;
        }
    }
    __syncthreads();

    // relu + store y transposed
    {
#pragma unroll
        for (int p = 0; p < 4; p++) {
#pragma unroll
            for (int j = 0; j < 8; j++) {
                float lo, hi;
                asm("mov.b64 {%0,%1},%2;" : "=f"(lo), "=f"(hi) : "l"(acc[p][j]));
                lo = fmaxf(lo, 0.f);
                hi = fmaxf(hi, 0.f);
                unsigned ya = zb + (unsigned)((j0 + j) * ZPAD + i0 + 2 * p) * 4;
                asm volatile("st.shared.v2.b32 [%0],{%1,%2};"
                             :: "r"(ya), "f"(lo), "f"(hi));
            }
        }
    }
    __syncthreads();

    // ================= GEMV 2: h = y @ W2 + b2 =================
    {
#pragma unroll
        for (int j = 0; j < 8; j++) {
            unsigned long long bd = dupf(sm[OFF_B2 + j0 + j]);
            acc[0][j] = bd; acc[1][j] = bd; acc[2][j] = bd; acc[3][j] = bd;
        }
        unsigned za = zb + i0 * 4;
#pragma unroll 4
        for (int k = 0; k < 64; k++) {
            unsigned long long z0, z1, z2, z3;
            asm("ld.shared.v2.u64 {%0,%1},[%2];" : "=l"(z0), "=l"(z1) : "r"(za));
            asm("ld.shared.v2.u64 {%0,%1},[%2];" : "=l"(z2), "=l"(z3) : "r"(za + 16));
#pragma unroll
            for (int j = 0; j < 8; j++) {
                unsigned long long wd = dupf(sm[OFF_W2 + k * WPAD + j0 + j]);
                FMA2(acc[0][j], z0, wd);
                FMA2(acc[1][j], z1, wd);
                FMA2(acc[2][j], z2, wd);
                FMA2(acc[3][j], z3, wd);
            }
            za += ZPAD * 4;
        }
    }

    if (!last) {
        // store h as fp16 (one 16B vector per node per thread)
#pragma unroll
        for (int p = 0; p < 4; p++) {
            int n0 = nbase + i0 + 2 * p;
            float lo[8], hi[8];
#pragma unroll
            for (int j = 0; j < 8; j++)
                asm("mov.b64 {%0,%1},%2;" : "=f"(lo[j]), "=f"(hi[j]) : "l"(acc[p][j]));
            if (n0 < N_NODES) {
                __half2 q0 = __floats2half2_rn(lo[0], lo[1]);
                __half2 q1 = __floats2half2_rn(lo[2], lo[3]);
                __half2 q2 = __floats2half2_rn(lo[4], lo[5]);
                __half2 q3 = __floats2half2_rn(lo[6], lo[7]);
                uint4 v = make_uint4(*(unsigned*)&q0, *(unsigned*)&q1,
                                     *(unsigned*)&q2, *(unsigned*)&q3);
                *(uint4*)(g_hh + n0 * HID + j0) = v;
            }
            if (n0 + 1 < N_NODES) {
                __half2 q0 = __floats2half2_rn(hi[0], hi[1]);
                __half2 q1 = __floats2half2_rn(hi[2], hi[3]);
                __half2 q2 = __floats2half2_rn(hi[4], hi[5]);
                __half2 q3 = __floats2half2_rn(hi[6], hi[7]);
                uint4 v = make_uint4(*(unsigned*)&q0, *(unsigned*)&q1,
                                     *(unsigned*)&q2, *(unsigned*)&q3);
                *(uint4*)(g_hh + (n0 + 1) * HID + j0) = v;
            }
        }
    } else {
        // fused pool + head
        float dot[8];
#pragma unroll
        for (int a = 0; a < 8; a++) dot[a] = 0.f;
#pragma unroll
        for (int j = 0; j < 8; j++) {
            float wr = __ldg(Wr + j0 + j);
#pragma unroll
            for (int p = 0; p < 4; p++) {
                float lo, hi;
                asm("mov.b64 {%0,%1},%2;" : "=f"(lo), "=f"(hi) : "l"(acc[p][j]));
                dot[2 * p]     = fmaf(lo, wr, dot[2 * p]);
                dot[2 * p + 1] = fmaf(hi, wr, dot[2 * p + 1]);
            }
        }
#pragma unroll
        for (int m = 1; m < 8; m <<= 1) {
#pragma unroll
            for (int a = 0; a < 8; a++)
                dot[a] += __shfl_xor_sync(0xffffffffu, dot[a], m);
        }
        if (jg == 0) {
#pragma unroll
            for (int a = 0; a < 8; a++) {
                int n = nbase + i0 + a;
                if (n < N_NODES)
                    atomicAdd(out + __ldg(gids + n), dot[a]);
            }
        }
    }
}

// ---------------------------------------------------------------------------
extern "C" void kernel_launch(void* const* d_in, const int* in_sizes, int n_in,
                              void* d_out, int out_size) {
    const int*   feats = (const int*)d_in[0];
    const int*   src   = (const int*)d_in[1];
    const int*   dst   = (const int*)d_in[2];
    const int*   gids  = (const int*)d_in[3];
    const float* emb   = (const float*)d_in[4];
    const float* W1    = (const float*)d_in[5];
    const float* b1    = (const float*)d_in[6];
    const float* W2    = (const float*)d_in[7];
    const float* b2    = (const float*)d_in[8];
    const float* Wr    = (const float*)d_in[9];
    float* out = (float*)d_out;

    cudaFuncSetAttribute(mlp_kernel,
                         cudaFuncAttributeMaxDynamicSharedMemorySize, SMEM_BYTES);

    // CSR build (padded rows) + prep — 3 kernels total
    setup_kernel<<<(CSR_CAP / 4 + 255) / 256, 256>>>(dst, feats, emb, out);
    scan_kernel<<<SCAN_BLKS, 1024>>>();
    scatter_kernel<<<(N_EDGES / 4 + 255) / 256, 256>>>(src, dst);

    // 3 GIN layers
    const int a0blk = (N_NODES * 16 + 255) / 256;
    const int ablk  = (N_NODES * 8 + 255) / 256;
    const int mblk  = (N_NODES + NPB - 1) / NPB;

    agg0_kernel<<<a0blk, 256>>>();
    mlp_kernel<<<mblk, 128, SMEM_BYTES>>>(W1, b1, W2, b2, 0, 0, gids, Wr, out);
    agg_kernel<<<ablk, 256>>>();
    mlp_kernel<<<mblk, 128, SMEM_BYTES>>>(W1, b1, W2, b2, 1, 0, gids, Wr, out);
    agg_kernel<<<ablk, 256>>>();
    mlp_kernel<<<mblk, 128, SMEM_BYTES>>>(W1, b1, W2, b2, 2, 1, gids, Wr, out);
}

// round 10
// speedup vs baseline: 1.7371x; 1.0208x over previous
#include <cuda_runtime.h>
#include <cuda_fp16.h>

#define N_NODES  50000
#define N_EDGES  800000
#define N_GRAPHS 128
#define HID      64
#define VOCAB    100
#define LAYERS   3
#define NPB      128                          // nodes per block in mlp kernel
#define CSR_CAP  (N_EDGES + 7 * N_NODES)      // padded CSR capacity
#define SCAN_BLKS ((N_NODES + 1023) / 1024)   // 49

// Scratch (__device__ globals — allocation-free rule).
// Row N_NODES of g_hh is a permanent ZERO row (never written): padded-CSR
// dummy gather target. Row VOCAB of g_emb_pad likewise (csr_feat padding).
// g_deg invariant: zero at entry to every call (static init; scan_kernel
// re-zeros it after reading). g_blk_agg zeroed by setup_kernel each call.
__device__ __half g_hh[(N_NODES + 1) * HID];   // fp16 inter-layer h (128B/row)
__device__ __half g_zh[N_NODES * HID];         // fp16 aggregated z (128B/row)
__device__ float  g_emb_pad[(VOCAB + 1) * HID];
__device__ int    g_feats_pad[N_NODES + 1];
__device__ int    g_deg[N_NODES];
__device__ int    g_rowptr[N_NODES + 1];
__device__ int    g_pos[N_NODES];
__device__ int    g_blk_agg[SCAN_BLKS];
__device__ int    g_csr_src[CSR_CAP];
__device__ int    g_csr_feat[CSR_CAP];

// ---------------------------------------------------------------------------
// Setup: CSR pad-fill + degree histogram + padded emb/feats + zero out/agg
// ---------------------------------------------------------------------------
__global__ void setup_kernel(const int* __restrict__ dst,
                             const int* __restrict__ feats,
                             const float* __restrict__ emb,
                             float* __restrict__ out) {
    int i = blockIdx.x * blockDim.x + threadIdx.x;
    if (i * 4 < CSR_CAP) {
        ((int4*)g_csr_src)[i]  = make_int4(N_NODES, N_NODES, N_NODES, N_NODES);
        ((int4*)g_csr_feat)[i] = make_int4(VOCAB, VOCAB, VOCAB, VOCAB);
    }
    if (i * 4 < N_EDGES) {
        int4 d = ((const int4*)dst)[i];
        atomicAdd(&g_deg[d.x], 1);
        atomicAdd(&g_deg[d.y], 1);
        atomicAdd(&g_deg[d.z], 1);
        atomicAdd(&g_deg[d.w], 1);
    }
    if (i < (VOCAB + 1) * HID)
        g_emb_pad[i] = (i < VOCAB * HID) ? emb[i] : 0.f;
    if (i < N_NODES)       g_feats_pad[i] = __ldg(feats + i);
    else if (i == N_NODES) g_feats_pad[i] = VOCAB;
    if (i < SCAN_BLKS) g_blk_agg[i] = 0;
    if (i < N_GRAPHS)  out[i] = 0.f;
}

// ---------------------------------------------------------------------------
// Single-pass scan of PADDED degrees (x8) -> rowptr + pos; re-zeros g_deg.
// 49 blocks all resident in one wave -> spin on predecessor aggregates safe.
// ---------------------------------------------------------------------------
__global__ void __launch_bounds__(1024) scan_kernel() {
    __shared__ int warp_sums[32];
    __shared__ int block_prefix;
    const int t = threadIdx.x, b = blockIdx.x;
    const int lane = t & 31, warp = t >> 5;
    if (t == 0) block_prefix = 0;

    int i = b * 1024 + t;
    int d = 0;
    if (i < N_NODES) {
        d = (g_deg[i] + 7) & ~7;
        g_deg[i] = 0;
    }

    int incl = d;
#pragma unroll
    for (int off = 1; off < 32; off <<= 1) {
        int u = __shfl_up_sync(0xffffffffu, incl, off);
        if (lane >= off) incl += u;
    }
    if (lane == 31) warp_sums[warp] = incl;
    __syncthreads();

    if (warp == 0) {
        int v = warp_sums[lane];
        int w = v;
#pragma unroll
        for (int off = 1; off < 32; off <<= 1) {
            int u = __shfl_up_sync(0xffffffffu, w, off);
            if (lane >= off) w += u;
        }
        warp_sums[lane] = w;
    }
    __syncthreads();

    int wexcl = (warp > 0) ? warp_sums[warp - 1] : 0;
    int excl  = wexcl + incl - d;
    int block_total = warp_sums[31];

    if (t == 0)
        *(volatile int*)&g_blk_agg[b] = block_total + 1;

    if (t < b) {
        int v;
        do { v = *(volatile int*)&g_blk_agg[t]; } while (v == 0);
        atomicAdd(&block_prefix, v - 1);
    }
    __syncthreads();

    int r = block_prefix + excl;
    if (i < N_NODES) {
        g_rowptr[i] = r;
        g_pos[i]    = r;
    }
    if (b == SCAN_BLKS - 1 && t == 1023)
        g_rowptr[N_NODES] = block_prefix + excl + d;
}

// ---------------------------------------------------------------------------
// Scatter: CSR src indices AND pre-translated feat indices (for agg0).
// ---------------------------------------------------------------------------
__global__ void scatter_kernel(const int* __restrict__ src,
                               const int* __restrict__ dst) {
    int i = blockIdx.x * blockDim.x + threadIdx.x;
    if (i * 4 >= N_EDGES) return;
    int4 s = ((const int4*)src)[i];
    int4 d = ((const int4*)dst)[i];
    int f0 = __ldg(&g_feats_pad[s.x]);
    int f1 = __ldg(&g_feats_pad[s.y]);
    int f2 = __ldg(&g_feats_pad[s.z]);
    int f3 = __ldg(&g_feats_pad[s.w]);
    int p;
    p = atomicAdd(&g_pos[d.x], 1); g_csr_src[p] = s.x; g_csr_feat[p] = f0;
    p = atomicAdd(&g_pos[d.y], 1); g_csr_src[p] = s.y; g_csr_feat[p] = f1;
    p = atomicAdd(&g_pos[d.z], 1); g_csr_src[p] = s.z; g_csr_feat[p] = f2;
    p = atomicAdd(&g_pos[d.w], 1); g_csr_src[p] = s.w; g_csr_feat[p] = f3;
}

// ---------------------------------------------------------------------------
// Layer-0 aggregation from the (L1-resident, 25KB) fp32 embedding table via
// PRE-TRANSLATED feat indices: z[n] = emb[f[n]] + sum emb[csr_feat[e]].
// ---------------------------------------------------------------------------
__global__ void __launch_bounds__(256)
agg0_kernel() {
    int i = blockIdx.x * blockDim.x + threadIdx.x;
    if (i >= N_NODES * 16) return;
    int n = i >> 4;
    int c = i & 15;
    const float4* e4 = (const float4*)g_emb_pad;

    float4 acc = e4[__ldg(&g_feats_pad[n]) * 16 + c];
    int e   = __ldg(&g_rowptr[n]);
    int end = __ldg(&g_rowptr[n + 1]);

    for (; e < end; e += 8) {
        int4 fa = *(const int4*)&g_csr_feat[e];
        int4 fb = *(const int4*)&g_csr_feat[e + 4];
        float4 v0 = e4[fa.x * 16 + c];
        float4 v1 = e4[fa.y * 16 + c];
        float4 v2 = e4[fa.z * 16 + c];
        float4 v3 = e4[fa.w * 16 + c];
        float4 v4 = e4[fb.x * 16 + c];
        float4 v5 = e4[fb.y * 16 + c];
        float4 v6 = e4[fb.z * 16 + c];
        float4 v7 = e4[fb.w * 16 + c];
        acc.x += v0.x; acc.y += v0.y; acc.z += v0.z; acc.w += v0.w;
        acc.x += v1.x; acc.y += v1.y; acc.z += v1.z; acc.w += v1.w;
        acc.x += v2.x; acc.y += v2.y; acc.z += v2.z; acc.w += v2.w;
        acc.x += v3.x; acc.y += v3.y; acc.z += v3.z; acc.w += v3.w;
        acc.x += v4.x; acc.y += v4.y; acc.z += v4.z; acc.w += v4.w;
        acc.x += v5.x; acc.y += v5.y; acc.z += v5.z; acc.w += v5.w;
        acc.x += v6.x; acc.y += v6.y; acc.z += v6.z; acc.w += v6.w;
        acc.x += v7.x; acc.y += v7.y; acc.z += v7.z; acc.w += v7.w;
    }
    __half2 q0 = __floats2half2_rn(acc.x, acc.y);
    __half2 q1 = __floats2half2_rn(acc.z, acc.w);
    ((uint2*)g_zh)[n * 16 + c] = make_uint2(*(unsigned*)&q0, *(unsigned*)&q1);
}

// ---------------------------------------------------------------------------
// Layers 1,2 aggregation (fp16 h): z[n] = h[n] + sum h[s], fp32 accumulate,
// fp16 z out. 8 threads/node, one uint4 (8 halves) each. Padded CSR, 8-deep.
// ---------------------------------------------------------------------------
__device__ __forceinline__ void acc8h(float4& A, float4& B, uint4 u) {
    float2 f;
    f = __half22float2(*(const __half2*)&u.x); A.x += f.x; A.y += f.y;
    f = __half22float2(*(const __half2*)&u.y); A.z += f.x; A.w += f.y;
    f = __half22float2(*(const __half2*)&u.z); B.x += f.x; B.y += f.y;
    f = __half22float2(*(const __half2*)&u.w); B.z += f.x; B.w += f.y;
}

__global__ void __launch_bounds__(256)
agg_kernel() {
    int i = blockIdx.x * blockDim.x + threadIdx.x;
    if (i >= N_NODES * 8) return;
    int n = i >> 3;
    int c = i & 7;
    const uint4* hh = (const uint4*)g_hh;

    float4 A = {0.f, 0.f, 0.f, 0.f}, B = {0.f, 0.f, 0.f, 0.f};
    acc8h(A, B, hh[n * 8 + c]);          // self term

    int e   = __ldg(&g_rowptr[n]);
    int end = __ldg(&g_rowptr[n + 1]);
    for (; e < end; e += 8) {
        int4 sa = *(const int4*)&g_csr_src[e];
        int4 sb = *(const int4*)&g_csr_src[e + 4];
        uint4 u0 = hh[sa.x * 8 + c];
        uint4 u1 = hh[sa.y * 8 + c];
        uint4 u2 = hh[sa.z * 8 + c];
        uint4 u3 = hh[sa.w * 8 + c];
        uint4 u4 = hh[sb.x * 8 + c];
        uint4 u5 = hh[sb.y * 8 + c];
        uint4 u6 = hh[sb.z * 8 + c];
        uint4 u7 = hh[sb.w * 8 + c];
        acc8h(A, B, u0);
        acc8h(A, B, u1);
        acc8h(A, B, u2);
        acc8h(A, B, u3);
        acc8h(A, B, u4);
        acc8h(A, B, u5);
        acc8h(A, B, u6);
        acc8h(A, B, u7);
    }
    __half2 q0 = __floats2half2_rn(A.x, A.y);
    __half2 q1 = __floats2half2_rn(A.z, A.w);
    __half2 q2 = __floats2half2_rn(B.x, B.y);
    __half2 q3 = __floats2half2_rn(B.z, B.w);
    ((uint4*)g_zh)[n * 8 + c] = make_uint4(*(unsigned*)&q0, *(unsigned*)&q1,
                                           *(unsigned*)&q2, *(unsigned*)&q3);
}

// ---------------------------------------------------------------------------
// MLP: h = relu(z@W1+b1)@W2 + b2, z in fp16, h out fp16 (128B/node).
// 128 threads, 128 nodes/block. Thread = 8 nodes x 8 cols (node-paired fma2).
// LAST layer: fused pool+head instead of the h store.
// ---------------------------------------------------------------------------
#define OFF_W1 0
#define OFF_W2 4352
#define OFF_B1 8704
#define OFF_B2 8768
#define OFF_Z  8832
#define WPAD   68
#define ZPAD   132
#define SMEM_BYTES (17280 * 4)

__device__ __forceinline__ unsigned su32(const void* p) {
    return (unsigned)__cvta_generic_to_shared(p);
}
__device__ __forceinline__ unsigned long long dupf(float x) {
    unsigned long long r;
    asm("mov.b64 %0, {%1, %1};" : "=l"(r) : "f"(x));
    return r;
}
#define FMA2(d, a, b) asm("fma.rn.f32x2 %0, %1, %2, %0;" : "+l"(d) : "l"(a), "l"(b))

__global__ void __launch_bounds__(128)
mlp_kernel(const float* __restrict__ W1, const float* __restrict__ b1,
           const float* __restrict__ W2, const float* __restrict__ b2,
           int layer, int last,
           const int* __restrict__ gids, const float* __restrict__ Wr,
           float* __restrict__ out) {
    extern __shared__ __align__(16) float sm[];
    const int tid = threadIdx.x;
    const int nbase = blockIdx.x * NPB;

    // ---- stage weights/biases ----
    {
        const float4* w1 = (const float4*)(W1 + layer * HID * HID);
        const float4* w2 = (const float4*)(W2 + layer * HID * HID);
        for (int idx = tid; idx < 1024; idx += 128) {
            int r = idx >> 4, c = idx & 15;
            *(float4*)&sm[OFF_W1 + r * WPAD + c * 4] = w1[idx];
            *(float4*)&sm[OFF_W2 + r * WPAD + c * 4] = w2[idx];
        }
        if (tid < HID) {
            sm[OFF_B1 + tid] = b1[layer * HID + tid];
            sm[OFF_B2 + tid] = b2[layer * HID + tid];
        }
    }

    // ---- stage z (fp16 in gmem) transposed to fp32 smem: sz[k][node] ----
    {
        int n = nbase + tid;
        float v[64];
        if (n < N_NODES) {
            const uint4* zr = (const uint4*)(g_zh + n * HID);
#pragma unroll
            for (int q = 0; q < 8; q++) {
                uint4 u = zr[q];
                float2 f;
                f = __half22float2(*(const __half2*)&u.x);
                v[8 * q + 0] = f.x; v[8 * q + 1] = f.y;
                f = __half22float2(*(const __half2*)&u.y);
                v[8 * q + 2] = f.x; v[8 * q + 3] = f.y;
                f = __half22float2(*(const __half2*)&u.z);
                v[8 * q + 4] = f.x; v[8 * q + 5] = f.y;
                f = __half22float2(*(const __half2*)&u.w);
                v[8 * q + 6] = f.x; v[8 * q + 7] = f.y;
            }
        } else {
#pragma unroll
            for (int q = 0; q < 64; q++) v[q] = 0.f;
        }
#pragma unroll
        for (int k = 0; k < 64; k++) sm[OFF_Z + k * ZPAD + tid] = v[k];
    }
    __syncthreads();

    const int jg = tid & 7;          // col group: cols j0..j0+7
    const int ig = tid >> 3;         // node group: nodes i0..i0+7
    const int j0 = jg * 8;
    const int i0 = ig * 8;
    const unsigned zb = su32(sm + OFF_Z);

    unsigned long long acc[4][8];

    // ================= GEMV 1: y = relu(z @ W1 + b1) =================
    {
#pragma unroll
        for (int j = 0; j < 8; j++) {
            unsigned long long bd = dupf(sm[OFF_B1 + j0 + j]);
            acc[0][j] = bd; acc[1][j] = bd; acc[2][j] = bd; acc[3][j] = bd;
        }
        unsigned za = zb + i0 * 4;
#pragma unroll 4
        for (int k = 0; k < 64; k++) {
            unsigned long long z0, z1, z2, z3;
            asm("ld.shared.v2.u64 {%0,%1},[%2];" : "=l"(z0), "=l"(z1) : "r"(za));
            asm("ld.shared.v2.u64 {%0,%1},[%2];" : "=l"(z2), "=l"(z3) : "r"(za + 16));
#pragma unroll
            for (int j = 0; j < 8; j++) {
                unsigned long long wd = dupf(sm[OFF_W1 + k * WPAD + j0 + j]);
                FMA2(acc[0][j], z0, wd);
                FMA2(acc[1][j], z1, wd);
                FMA2(acc[2][j], z2, wd);
                FMA2(acc[3][j], z3, wd);
            }
            za += ZPAD * 4;
        }
    }
    __syncthreads();

    // relu + store y transposed
    {
#pragma unroll
        for (int p = 0; p < 4; p++) {
#pragma unroll
            for (int j = 0; j < 8; j++) {
                float lo, hi;
                asm("mov.b64 {%0,%1},%2;" : "=f"(lo), "=f"(hi) : "l"(acc[p][j]));
                lo = fmaxf(lo, 0.f);
                hi = fmaxf(hi, 0.f);
                unsigned ya = zb + (unsigned)((j0 + j) * ZPAD + i0 + 2 * p) * 4;
                asm volatile("st.shared.v2.b32 [%0],{%1,%2};"
                             :: "r"(ya), "f"(lo), "f"(hi));
            }
        }
    }
    __syncthreads();

    // ================= GEMV 2: h = y @ W2 + b2 =================
    {
#pragma unroll
        for (int j = 0; j < 8; j++) {
            unsigned long long bd = dupf(sm[OFF_B2 + j0 + j]);
            acc[0][j] = bd; acc[1][j] = bd; acc[2][j] = bd; acc[3][j] = bd;
        }
        unsigned za = zb + i0 * 4;
#pragma unroll 4
        for (int k = 0; k < 64; k++) {
            unsigned long long z0, z1, z2, z3;
            asm("ld.shared.v2.u64 {%0,%1},[%2];" : "=l"(z0), "=l"(z1) : "r"(za));
            asm("ld.shared.v2.u64 {%0,%1},[%2];" : "=l"(z2), "=l"(z3) : "r"(za + 16));
#pragma unroll
            for (int j = 0; j < 8; j++) {
                unsigned long long wd = dupf(sm[OFF_W2 + k * WPAD + j0 + j]);
                FMA2(acc[0][j], z0, wd);
                FMA2(acc[1][j], z1, wd);
                FMA2(acc[2][j], z2, wd);
                FMA2(acc[3][j], z3, wd);
            }
            za += ZPAD * 4;
        }
    }

    if (!last) {
        // store h as fp16 (one 16B vector per node per thread)
#pragma unroll
        for (int p = 0; p < 4; p++) {
            int n0 = nbase + i0 + 2 * p;
            float lo[8], hi[8];
#pragma unroll
            for (int j = 0; j < 8; j++)
                asm("mov.b64 {%0,%1},%2;" : "=f"(lo[j]), "=f"(hi[j]) : "l"(acc[p][j]));
            if (n0 < N_NODES) {
                __half2 q0 = __floats2half2_rn(lo[0], lo[1]);
                __half2 q1 = __floats2half2_rn(lo[2], lo[3]);
                __half2 q2 = __floats2half2_rn(lo[4], lo[5]);
                __half2 q3 = __floats2half2_rn(lo[6], lo[7]);
                uint4 v = make_uint4(*(unsigned*)&q0, *(unsigned*)&q1,
                                     *(unsigned*)&q2, *(unsigned*)&q3);
                *(uint4*)(g_hh + n0 * HID + j0) = v;
            }
            if (n0 + 1 < N_NODES) {
                __half2 q0 = __floats2half2_rn(hi[0], hi[1]);
                __half2 q1 = __floats2half2_rn(hi[2], hi[3]);
                __half2 q2 = __floats2half2_rn(hi[4], hi[5]);
                __half2 q3 = __floats2half2_rn(hi[6], hi[7]);
                uint4 v = make_uint4(*(unsigned*)&q0, *(unsigned*)&q1,
                                     *(unsigned*)&q2, *(unsigned*)&q3);
                *(uint4*)(g_hh + (n0 + 1) * HID + j0) = v;
            }
        }
    } else {
        // fused pool + head
        float dot[8];
#pragma unroll
        for (int a = 0; a < 8; a++) dot[a] = 0.f;
#pragma unroll
        for (int j = 0; j < 8; j++) {
            float wr = __ldg(Wr + j0 + j);
#pragma unroll
            for (int p = 0; p < 4; p++) {
                float lo, hi;
                asm("mov.b64 {%0,%1},%2;" : "=f"(lo), "=f"(hi) : "l"(acc[p][j]));
                dot[2 * p]     = fmaf(lo, wr, dot[2 * p]);
                dot[2 * p + 1] = fmaf(hi, wr, dot[2 * p + 1]);
            }
        }
#pragma unroll
        for (int m = 1; m < 8; m <<= 1) {
#pragma unroll
            for (int a = 0; a < 8; a++)
                dot[a] += __shfl_xor_sync(0xffffffffu, dot[a], m);
        }
        if (jg == 0) {
#pragma unroll
            for (int a = 0; a < 8; a++) {
                int n = nbase + i0 + a;
                if (n < N_NODES)
                    atomicAdd(out + __ldg(gids + n), dot[a]);
            }
        }
    }
}

// ---------------------------------------------------------------------------
extern "C" void kernel_launch(void* const* d_in, const int* in_sizes, int n_in,
                              void* d_out, int out_size) {
    const int*   feats = (const int*)d_in[0];
    const int*   src   = (const int*)d_in[1];
    const int*   dst   = (const int*)d_in[2];
    const int*   gids  = (const int*)d_in[3];
    const float* emb   = (const float*)d_in[4];
    const float* W1    = (const float*)d_in[5];
    const float* b1    = (const float*)d_in[6];
    const float* W2    = (const float*)d_in[7];
    const float* b2    = (const float*)d_in[8];
    const float* Wr    = (const float*)d_in[9];
    float* out = (float*)d_out;

    cudaFuncSetAttribute(mlp_kernel,
                         cudaFuncAttributeMaxDynamicSharedMemorySize, SMEM_BYTES);

    // CSR build (padded rows) + prep — 3 kernels
    setup_kernel<<<(CSR_CAP / 4 + 255) / 256, 256>>>(dst, feats, emb, out);
    scan_kernel<<<SCAN_BLKS, 1024>>>();
    scatter_kernel<<<(N_EDGES / 4 + 255) / 256, 256>>>(src, dst);

    // 3 GIN layers
    const int a0blk = (N_NODES * 16 + 255) / 256;
    const int ablk  = (N_NODES * 8 + 255) / 256;
    const int mblk  = (N_NODES + NPB - 1) / NPB;

    agg0_kernel<<<a0blk, 256>>>();
    mlp_kernel<<<mblk, 128, SMEM_BYTES>>>(W1, b1, W2, b2, 0, 0, gids, Wr, out);
    agg_kernel<<<ablk, 256>>>();
    mlp_kernel<<<mblk, 128, SMEM_BYTES>>>(W1, b1, W2, b2, 1, 0, gids, Wr, out);
    agg_kernel<<<ablk, 256>>>();
    mlp_kernel<<<mblk, 128, SMEM_BYTES>>>(W1, b1, W2, b2, 2, 1, gids, Wr, out);
}

// round 11
// speedup vs baseline: 1.8179x; 1.0465x over previous
#include <cuda_runtime.h>
#include <cuda_fp16.h>

#define N_NODES  50000
#define N_EDGES  800000
#define N_GRAPHS 128
#define HID      64
#define VOCAB    100
#define LAYERS   3
#define NPB      128                          // nodes per block in mlp kernel
#define CSR_CAP  (N_EDGES + 7 * N_NODES)      // padded CSR capacity
#define SCAN_BLKS ((N_NODES + 1023) / 1024)   // 49

// Scratch (__device__ globals — allocation-free rule).
// Row N_NODES of g_hh and row VOCAB of g_embh are permanent ZERO rows
// (never written): padded-CSR dummy gather targets.
// g_deg invariant: zero at entry (static init; scan_kernel re-zeros).
__device__ __half g_hh[(N_NODES + 1) * HID];   // fp16 inter-layer h (128B/row)
__device__ __half g_zh[N_NODES * HID];         // fp16 aggregated z (128B/row)
__device__ __half g_embh[(VOCAB + 1) * HID];   // fp16 embedding (L1-resident)
__device__ int    g_feats_pad[N_NODES + 1];
__device__ int    g_deg[N_NODES];
__device__ int    g_rowptr[N_NODES + 1];
__device__ int    g_pos[N_NODES];
__device__ int    g_blk_agg[SCAN_BLKS];
__device__ int2   g_csr[CSR_CAP];              // (src, feat[src]) per edge

// ---------------------------------------------------------------------------
// Setup: CSR pad-fill + degree histogram + fp16 emb + padded feats + zeroing
// ---------------------------------------------------------------------------
__global__ void setup_kernel(const int* __restrict__ dst,
                             const int* __restrict__ feats,
                             const float* __restrict__ emb,
                             float* __restrict__ out) {
    int i = blockIdx.x * blockDim.x + threadIdx.x;
    // fill merged CSR with dummy pairs (2 int4 = 4 int2 entries per thread)
    if (i * 4 < CSR_CAP) {
        int4 pad = make_int4(N_NODES, VOCAB, N_NODES, VOCAB);
        ((int4*)g_csr)[2 * i]     = pad;
        ((int4*)g_csr)[2 * i + 1] = pad;
    }
    if (i * 4 < N_EDGES) {
        int4 d = ((const int4*)dst)[i];
        atomicAdd(&g_deg[d.x], 1);
        atomicAdd(&g_deg[d.y], 1);
        atomicAdd(&g_deg[d.z], 1);
        atomicAdd(&g_deg[d.w], 1);
    }
    if (i < (VOCAB + 1) * HID)
        g_embh[i] = __float2half_rn((i < VOCAB * HID) ? emb[i] : 0.f);
    if (i < N_NODES)       g_feats_pad[i] = __ldg(feats + i);
    else if (i == N_NODES) g_feats_pad[i] = VOCAB;
    if (i < SCAN_BLKS) g_blk_agg[i] = 0;
    if (i < N_GRAPHS)  out[i] = 0.f;
}

// ---------------------------------------------------------------------------
// Single-pass scan of PADDED degrees (x8) -> rowptr + pos; re-zeros g_deg.
// 49 blocks all resident in one wave -> spin on predecessor aggregates safe.
// ---------------------------------------------------------------------------
__global__ void __launch_bounds__(1024) scan_kernel() {
    __shared__ int warp_sums[32];
    __shared__ int block_prefix;
    const int t = threadIdx.x, b = blockIdx.x;
    const int lane = t & 31, warp = t >> 5;
    if (t == 0) block_prefix = 0;

    int i = b * 1024 + t;
    int d = 0;
    if (i < N_NODES) {
        d = (g_deg[i] + 7) & ~7;
        g_deg[i] = 0;
    }

    int incl = d;
#pragma unroll
    for (int off = 1; off < 32; off <<= 1) {
        int u = __shfl_up_sync(0xffffffffu, incl, off);
        if (lane >= off) incl += u;
    }
    if (lane == 31) warp_sums[warp] = incl;
    __syncthreads();

    if (warp == 0) {
        int v = warp_sums[lane];
        int w = v;
#pragma unroll
        for (int off = 1; off < 32; off <<= 1) {
            int u = __shfl_up_sync(0xffffffffu, w, off);
            if (lane >= off) w += u;
        }
        warp_sums[lane] = w;
    }
    __syncthreads();

    int wexcl = (warp > 0) ? warp_sums[warp - 1] : 0;
    int excl  = wexcl + incl - d;
    int block_total = warp_sums[31];

    if (t == 0)
        *(volatile int*)&g_blk_agg[b] = block_total + 1;

    if (t < b) {
        int v;
        do { v = *(volatile int*)&g_blk_agg[t]; } while (v == 0);
        atomicAdd(&block_prefix, v - 1);
    }
    __syncthreads();

    int r = block_prefix + excl;
    if (i < N_NODES) {
        g_rowptr[i] = r;
        g_pos[i]    = r;
    }
    if (b == SCAN_BLKS - 1 && t == 1023)
        g_rowptr[N_NODES] = block_prefix + excl + d;
}

// ---------------------------------------------------------------------------
// Scatter: one 8B (src, feat) store per edge into the merged CSR.
// ---------------------------------------------------------------------------
__global__ void scatter_kernel(const int* __restrict__ src,
                               const int* __restrict__ dst) {
    int i = blockIdx.x * blockDim.x + threadIdx.x;
    if (i * 4 >= N_EDGES) return;
    int4 s = ((const int4*)src)[i];
    int4 d = ((const int4*)dst)[i];
    int f0 = __ldg(&g_feats_pad[s.x]);
    int f1 = __ldg(&g_feats_pad[s.y]);
    int f2 = __ldg(&g_feats_pad[s.z]);
    int f3 = __ldg(&g_feats_pad[s.w]);
    int p;
    p = atomicAdd(&g_pos[d.x], 1); g_csr[p] = make_int2(s.x, f0);
    p = atomicAdd(&g_pos[d.y], 1); g_csr[p] = make_int2(s.y, f1);
    p = atomicAdd(&g_pos[d.z], 1); g_csr[p] = make_int2(s.z, f2);
    p = atomicAdd(&g_pos[d.w], 1); g_csr[p] = make_int2(s.w, f3);
}

// ---------------------------------------------------------------------------
// Unified aggregation (both layer-0 and later layers):
//   mode=1: z[n] = embh[feat[n]] + sum embh[csr[e].y]   (fp16 emb table)
//   mode=0: z[n] = hh[n]        + sum hh[csr[e].x]      (fp16 h)
// 8 threads/node, one uint4 (8 halves) each, fp32 accumulate, fp16 z out.
// Padded CSR rows (x8) -> no remainder, 8-deep independent batches.
// ---------------------------------------------------------------------------
__device__ __forceinline__ void acc8h(float4& A, float4& B, uint4 u) {
    float2 f;
    f = __half22float2(*(const __half2*)&u.x); A.x += f.x; A.y += f.y;
    f = __half22float2(*(const __half2*)&u.y); A.z += f.x; A.w += f.y;
    f = __half22float2(*(const __half2*)&u.z); B.x += f.x; B.y += f.y;
    f = __half22float2(*(const __half2*)&u.w); B.z += f.x; B.w += f.y;
}

__global__ void __launch_bounds__(256)
agg_kernel(int mode) {
    int i = blockIdx.x * blockDim.x + threadIdx.x;
    if (i >= N_NODES * 8) return;
    int n = i >> 3;
    int c = i & 7;
    const uint4* tab = mode ? (const uint4*)g_embh : (const uint4*)g_hh;

    float4 A = {0.f, 0.f, 0.f, 0.f}, B = {0.f, 0.f, 0.f, 0.f};
    int self = mode ? __ldg(&g_feats_pad[n]) : n;
    acc8h(A, B, tab[self * 8 + c]);

    int e   = __ldg(&g_rowptr[n]);
    int end = __ldg(&g_rowptr[n + 1]);
    for (; e < end; e += 8) {
        int4 p0 = *(const int4*)&g_csr[e];       // (s,f, s,f) edges e,e+1
        int4 p1 = *(const int4*)&g_csr[e + 2];
        int4 p2 = *(const int4*)&g_csr[e + 4];
        int4 p3 = *(const int4*)&g_csr[e + 6];
        int s0 = mode ? p0.y : p0.x;
        int s1 = mode ? p0.w : p0.z;
        int s2 = mode ? p1.y : p1.x;
        int s3 = mode ? p1.w : p1.z;
        int s4 = mode ? p2.y : p2.x;
        int s5 = mode ? p2.w : p2.z;
        int s6 = mode ? p3.y : p3.x;
        int s7 = mode ? p3.w : p3.z;
        uint4 u0 = tab[s0 * 8 + c];
        uint4 u1 = tab[s1 * 8 + c];
        uint4 u2 = tab[s2 * 8 + c];
        uint4 u3 = tab[s3 * 8 + c];
        uint4 u4 = tab[s4 * 8 + c];
        uint4 u5 = tab[s5 * 8 + c];
        uint4 u6 = tab[s6 * 8 + c];
        uint4 u7 = tab[s7 * 8 + c];
        acc8h(A, B, u0);
        acc8h(A, B, u1);
        acc8h(A, B, u2);
        acc8h(A, B, u3);
        acc8h(A, B, u4);
        acc8h(A, B, u5);
        acc8h(A, B, u6);
        acc8h(A, B, u7);
    }
    __half2 q0 = __floats2half2_rn(A.x, A.y);
    __half2 q1 = __floats2half2_rn(A.z, A.w);
    __half2 q2 = __floats2half2_rn(B.x, B.y);
    __half2 q3 = __floats2half2_rn(B.z, B.w);
    ((uint4*)g_zh)[n * 8 + c] = make_uint4(*(unsigned*)&q0, *(unsigned*)&q1,
                                           *(unsigned*)&q2, *(unsigned*)&q3);
}

// ---------------------------------------------------------------------------
// MLP: h = relu(z@W1+b1)@W2 + b2, z in fp16, h out fp16 (128B/node).
// 128 threads, 128 nodes/block. Thread = 8 nodes x 8 cols (node-paired fma2).
// LAST layer: fused pool+head instead of the h store.
// ---------------------------------------------------------------------------
#define OFF_W1 0
#define OFF_W2 4352
#define OFF_B1 8704
#define OFF_B2 8768
#define OFF_Z  8832
#define WPAD   68
#define ZPAD   132
#define SMEM_BYTES (17280 * 4)

__device__ __forceinline__ unsigned su32(const void* p) {
    return (unsigned)__cvta_generic_to_shared(p);
}
__device__ __forceinline__ unsigned long long dupf(float x) {
    unsigned long long r;
    asm("mov.b64 %0, {%1, %1};" : "=l"(r) : "f"(x));
    return r;
}
#define FMA2(d, a, b) asm("fma.rn.f32x2 %0, %1, %2, %0;" : "+l"(d) : "l"(a), "l"(b))

__global__ void __launch_bounds__(128)
mlp_kernel(const float* __restrict__ W1, const float* __restrict__ b1,
           const float* __restrict__ W2, const float* __restrict__ b2,
           int layer, int last,
           const int* __restrict__ gids, const float* __restrict__ Wr,
           float* __restrict__ out) {
    extern __shared__ __align__(16) float sm[];
    const int tid = threadIdx.x;
    const int nbase = blockIdx.x * NPB;

    // ---- stage weights/biases ----
    {
        const float4* w1 = (const float4*)(W1 + layer * HID * HID);
        const float4* w2 = (const float4*)(W2 + layer * HID * HID);
        for (int idx = tid; idx < 1024; idx += 128) {
            int r = idx >> 4, c = idx & 15;
            *(float4*)&sm[OFF_W1 + r * WPAD + c * 4] = w1[idx];
            *(float4*)&sm[OFF_W2 + r * WPAD + c * 4] = w2[idx];
        }
        if (tid < HID) {
            sm[OFF_B1 + tid] = b1[layer * HID + tid];
            sm[OFF_B2 + tid] = b2[layer * HID + tid];
        }
    }

    // ---- stage z (fp16 in gmem) transposed to fp32 smem: sz[k][node] ----
    {
        int n = nbase + tid;
        float v[64];
        if (n < N_NODES) {
            const uint4* zr = (const uint4*)(g_zh + n * HID);
#pragma unroll
            for (int q = 0; q < 8; q++) {
                uint4 u = zr[q];
                float2 f;
                f = __half22float2(*(const __half2*)&u.x);
                v[8 * q + 0] = f.x; v[8 * q + 1] = f.y;
                f = __half22float2(*(const __half2*)&u.y);
                v[8 * q + 2] = f.x; v[8 * q + 3] = f.y;
                f = __half22float2(*(const __half2*)&u.z);
                v[8 * q + 4] = f.x; v[8 * q + 5] = f.y;
                f = __half22float2(*(const __half2*)&u.w);
                v[8 * q + 6] = f.x; v[8 * q + 7] = f.y;
            }
        } else {
#pragma unroll
            for (int q = 0; q < 64; q++) v[q] = 0.f;
        }
#pragma unroll
        for (int k = 0; k < 64; k++) sm[OFF_Z + k * ZPAD + tid] = v[k];
    }
    __syncthreads();

    const int jg = tid & 7;          // col group: cols j0..j0+7
    const int ig = tid >> 3;         // node group: nodes i0..i0+7
    const int j0 = jg * 8;
    const int i0 = ig * 8;
    const unsigned zb = su32(sm + OFF_Z);

    unsigned long long acc[4][8];

    // ================= GEMV 1: y = relu(z @ W1 + b1) =================
    {
#pragma unroll
        for (int j = 0; j < 8; j++) {
            unsigned long long bd = dupf(sm[OFF_B1 + j0 + j]);
            acc[0][j] = bd; acc[1][j] = bd; acc[2][j] = bd; acc[3][j] = bd;
        }
        unsigned za = zb + i0 * 4;
#pragma unroll 4
        for (int k = 0; k < 64; k++) {
            unsigned long long z0, z1, z2, z3;
            asm("ld.shared.v2.u64 {%0,%1},[%2];" : "=l"(z0), "=l"(z1) : "r"(za));
            asm("ld.shared.v2.u64 {%0,%1},[%2];" : "=l"(z2), "=l"(z3) : "r"(za + 16));
#pragma unroll
            for (int j = 0; j < 8; j++) {
                unsigned long long wd = dupf(sm[OFF_W1 + k * WPAD + j0 + j]);
                FMA2(acc[0][j], z0, wd);
                FMA2(acc[1][j], z1, wd);
                FMA2(acc[2][j], z2, wd);
                FMA2(acc[3][j], z3, wd);
            }
            za += ZPAD * 4;
        }
    }
    __syncthreads();

    // relu + store y transposed
    {
#pragma unroll
        for (int p = 0; p < 4; p++) {
#pragma unroll
            for (int j = 0; j < 8; j++) {
                float lo, hi;
                asm("mov.b64 {%0,%1},%2;" : "=f"(lo), "=f"(hi) : "l"(acc[p][j]));
                lo = fmaxf(lo, 0.f);
                hi = fmaxf(hi, 0.f);
                unsigned ya = zb + (unsigned)((j0 + j) * ZPAD + i0 + 2 * p) * 4;
                asm volatile("st.shared.v2.b32 [%0],{%1,%2};"
                             :: "r"(ya), "f"(lo), "f"(hi));
            }
        }
    }
    __syncthreads();

    // ================= GEMV 2: h = y @ W2 + b2 =================
    {
#pragma unroll
        for (int j = 0; j < 8; j++) {
            unsigned long long bd = dupf(sm[OFF_B2 + j0 + j]);
            acc[0][j] = bd; acc[1][j] = bd; acc[2][j] = bd; acc[3][j] = bd;
        }
        unsigned za = zb + i0 * 4;
#pragma unroll 4
        for (int k = 0; k < 64; k++) {
            unsigned long long z0, z1, z2, z3;
            asm("ld.shared.v2.u64 {%0,%1},[%2];" : "=l"(z0), "=l"(z1) : "r"(za));
            asm("ld.shared.v2.u64 {%0,%1},[%2];" : "=l"(z2), "=l"(z3) : "r"(za + 16));
#pragma unroll
            for (int j = 0; j < 8; j++) {
                unsigned long long wd = dupf(sm[OFF_W2 + k * WPAD + j0 + j]);
                FMA2(acc[0][j], z0, wd);
                FMA2(acc[1][j], z1, wd);
                FMA2(acc[2][j], z2, wd);
                FMA2(acc[3][j], z3, wd);
            }
            za += ZPAD * 4;
        }
    }

    if (!last) {
        // store h as fp16 (one 16B vector per node per thread)
#pragma unroll
        for (int p = 0; p < 4; p++) {
            int n0 = nbase + i0 + 2 * p;
            float lo[8], hi[8];
#pragma unroll
            for (int j = 0; j < 8; j++)
                asm("mov.b64 {%0,%1},%2;" : "=f"(lo[j]), "=f"(hi[j]) : "l"(acc[p][j]));
            if (n0 < N_NODES) {
                __half2 q0 = __floats2half2_rn(lo[0], lo[1]);
                __half2 q1 = __floats2half2_rn(lo[2], lo[3]);
                __half2 q2 = __floats2half2_rn(lo[4], lo[5]);
                __half2 q3 = __floats2half2_rn(lo[6], lo[7]);
                uint4 v = make_uint4(*(unsigned*)&q0, *(unsigned*)&q1,
                                     *(unsigned*)&q2, *(unsigned*)&q3);
                *(uint4*)(g_hh + n0 * HID + j0) = v;
            }
            if (n0 + 1 < N_NODES) {
                __half2 q0 = __floats2half2_rn(hi[0], hi[1]);
                __half2 q1 = __floats2half2_rn(hi[2], hi[3]);
                __half2 q2 = __floats2half2_rn(hi[4], hi[5]);
                __half2 q3 = __floats2half2_rn(hi[6], hi[7]);
                uint4 v = make_uint4(*(unsigned*)&q0, *(unsigned*)&q1,
                                     *(unsigned*)&q2, *(unsigned*)&q3);
                *(uint4*)(g_hh + (n0 + 1) * HID + j0) = v;
            }
        }
    } else {
        // fused pool + head
        float dot[8];
#pragma unroll
        for (int a = 0; a < 8; a++) dot[a] = 0.f;
#pragma unroll
        for (int j = 0; j < 8; j++) {
            float wr = __ldg(Wr + j0 + j);
#pragma unroll
            for (int p = 0; p < 4; p++) {
                float lo, hi;
                asm("mov.b64 {%0,%1},%2;" : "=f"(lo), "=f"(hi) : "l"(acc[p][j]));
                dot[2 * p]     = fmaf(lo, wr, dot[2 * p]);
                dot[2 * p + 1] = fmaf(hi, wr, dot[2 * p + 1]);
            }
        }
#pragma unroll
        for (int m = 1; m < 8; m <<= 1) {
#pragma unroll
            for (int a = 0; a < 8; a++)
                dot[a] += __shfl_xor_sync(0xffffffffu, dot[a], m);
        }
        if (jg == 0) {
#pragma unroll
            for (int a = 0; a < 8; a++) {
                int n = nbase + i0 + a;
                if (n < N_NODES)
                    atomicAdd(out + __ldg(gids + n), dot[a]);
            }
        }
    }
}

// ---------------------------------------------------------------------------
extern "C" void kernel_launch(void* const* d_in, const int* in_sizes, int n_in,
                              void* d_out, int out_size) {
    const int*   feats = (const int*)d_in[0];
    const int*   src   = (const int*)d_in[1];
    const int*   dst   = (const int*)d_in[2];
    const int*   gids  = (const int*)d_in[3];
    const float* emb   = (const float*)d_in[4];
    const float* W1    = (const float*)d_in[5];
    const float* b1    = (const float*)d_in[6];
    const float* W2    = (const float*)d_in[7];
    const float* b2    = (const float*)d_in[8];
    const float* Wr    = (const float*)d_in[9];
    float* out = (float*)d_out;

    cudaFuncSetAttribute(mlp_kernel,
                         cudaFuncAttributeMaxDynamicSharedMemorySize, SMEM_BYTES);

    // CSR build (padded rows) + prep — 3 kernels
    setup_kernel<<<(CSR_CAP / 4 + 255) / 256, 256>>>(dst, feats, emb, out);
    scan_kernel<<<SCAN_BLKS, 1024>>>();
    scatter_kernel<<<(N_EDGES / 4 + 255) / 256, 256>>>(src, dst);

    // 3 GIN layers (agg mode=1 reads emb table; mode=0 reads h)
    const int ablk = (N_NODES * 8 + 255) / 256;
    const int mblk = (N_NODES + NPB - 1) / NPB;

    agg_kernel<<<ablk, 256>>>(1);
    mlp_kernel<<<mblk, 128, SMEM_BYTES>>>(W1, b1, W2, b2, 0, 0, gids, Wr, out);
    agg_kernel<<<ablk, 256>>>(0);
    mlp_kernel<<<mblk, 128, SMEM_BYTES>>>(W1, b1, W2, b2, 1, 0, gids, Wr, out);
    agg_kernel<<<ablk, 256>>>(0);
    mlp_kernel<<<mblk, 128, SMEM_BYTES>>>(W1, b1, W2, b2, 2, 1, gids, Wr, out);
}

// round 12
// speedup vs baseline: 2.5790x; 1.4187x over previous
#include <cuda_runtime.h>
#include <cuda_fp16.h>

#define N_NODES  50000
#define N_EDGES  800000
#define N_GRAPHS 128
#define HID      64
#define VOCAB    100
#define LAYERS   3
#define NPB      128                          // nodes per block in mlp kernel
#define CSR_CAP  (N_EDGES + 7 * N_NODES)      // padded CSR capacity
#define SCAN_BLKS ((N_NODES + 1023) / 1024)   // 49

// Scratch (__device__ globals — allocation-free rule).
// Row N_NODES of g_hh and row VOCAB of g_embh are permanent ZERO rows
// (never written): padded-CSR dummy gather targets.
// g_deg invariant: zero at entry (static init; scan_kernel re-zeros).
__device__ __half g_hh[(N_NODES + 1) * HID];   // fp16 inter-layer h (128B/row)
__device__ __half g_zh[N_NODES * HID];         // fp16 aggregated z (128B/row)
__device__ __half g_embh[(VOCAB + 1) * HID];   // fp16 embedding (L1-resident)
__device__ __half g_w1h[LAYERS * HID * HID];   // fp16 W1
__device__ __half g_w2h[LAYERS * HID * HID];   // fp16 W2
__device__ int    g_feats_pad[N_NODES + 1];
__device__ int    g_deg[N_NODES];
__device__ int    g_rowptr[N_NODES + 1];
__device__ int    g_pos[N_NODES];
__device__ int    g_blk_agg[SCAN_BLKS];
__device__ int2   g_csr[CSR_CAP];              // (src, feat[src]) per edge

__device__ __forceinline__ unsigned su32(const void* p) {
    return (unsigned)__cvta_generic_to_shared(p);
}

// ---------------------------------------------------------------------------
// Setup: CSR pad-fill + degree hist + fp16 emb/W1/W2 + padded feats + zeroing
// ---------------------------------------------------------------------------
__global__ void setup_kernel(const int* __restrict__ dst,
                             const int* __restrict__ feats,
                             const float* __restrict__ emb,
                             const float* __restrict__ W1,
                             const float* __restrict__ W2,
                             float* __restrict__ out) {
    int i = blockIdx.x * blockDim.x + threadIdx.x;
    if (i * 4 < CSR_CAP) {
        int4 pad = make_int4(N_NODES, VOCAB, N_NODES, VOCAB);
        ((int4*)g_csr)[2 * i]     = pad;
        ((int4*)g_csr)[2 * i + 1] = pad;
    }
    if (i * 4 < N_EDGES) {
        int4 d = ((const int4*)dst)[i];
        atomicAdd(&g_deg[d.x], 1);
        atomicAdd(&g_deg[d.y], 1);
        atomicAdd(&g_deg[d.z], 1);
        atomicAdd(&g_deg[d.w], 1);
    }
    if (i < (VOCAB + 1) * HID)
        g_embh[i] = __float2half_rn((i < VOCAB * HID) ? emb[i] : 0.f);
    if (i < LAYERS * HID * HID) {
        g_w1h[i] = __float2half_rn(W1[i]);
        g_w2h[i] = __float2half_rn(W2[i]);
    }
    if (i < N_NODES)       g_feats_pad[i] = __ldg(feats + i);
    else if (i == N_NODES) g_feats_pad[i] = VOCAB;
    if (i < SCAN_BLKS) g_blk_agg[i] = 0;
    if (i < N_GRAPHS)  out[i] = 0.f;
}

// ---------------------------------------------------------------------------
// Single-pass scan of PADDED degrees (x8) -> rowptr + pos; re-zeros g_deg.
// 49 blocks all resident in one wave -> spin on predecessor aggregates safe.
// ---------------------------------------------------------------------------
__global__ void __launch_bounds__(1024) scan_kernel() {
    __shared__ int warp_sums[32];
    __shared__ int block_prefix;
    const int t = threadIdx.x, b = blockIdx.x;
    const int lane = t & 31, warp = t >> 5;
    if (t == 0) block_prefix = 0;

    int i = b * 1024 + t;
    int d = 0;
    if (i < N_NODES) {
        d = (g_deg[i] + 7) & ~7;
        g_deg[i] = 0;
    }

    int incl = d;
#pragma unroll
    for (int off = 1; off < 32; off <<= 1) {
        int u = __shfl_up_sync(0xffffffffu, incl, off);
        if (lane >= off) incl += u;
    }
    if (lane == 31) warp_sums[warp] = incl;
    __syncthreads();

    if (warp == 0) {
        int v = warp_sums[lane];
        int w = v;
#pragma unroll
        for (int off = 1; off < 32; off <<= 1) {
            int u = __shfl_up_sync(0xffffffffu, w, off);
            if (lane >= off) w += u;
        }
        warp_sums[lane] = w;
    }
    __syncthreads();

    int wexcl = (warp > 0) ? warp_sums[warp - 1] : 0;
    int excl  = wexcl + incl - d;
    int block_total = warp_sums[31];

    if (t == 0)
        *(volatile int*)&g_blk_agg[b] = block_total + 1;

    if (t < b) {
        int v;
        do { v = *(volatile int*)&g_blk_agg[t]; } while (v == 0);
        atomicAdd(&block_prefix, v - 1);
    }
    __syncthreads();

    int r = block_prefix + excl;
    if (i < N_NODES) {
        g_rowptr[i] = r;
        g_pos[i]    = r;
    }
    if (b == SCAN_BLKS - 1 && t == 1023)
        g_rowptr[N_NODES] = block_prefix + excl + d;
}

// ---------------------------------------------------------------------------
// Scatter: one 8B (src, feat) store per edge into the merged CSR.
// ---------------------------------------------------------------------------
__global__ void scatter_kernel(const int* __restrict__ src,
                               const int* __restrict__ dst) {
    int i = blockIdx.x * blockDim.x + threadIdx.x;
    if (i * 4 >= N_EDGES) return;
    int4 s = ((const int4*)src)[i];
    int4 d = ((const int4*)dst)[i];
    int f0 = __ldg(&g_feats_pad[s.x]);
    int f1 = __ldg(&g_feats_pad[s.y]);
    int f2 = __ldg(&g_feats_pad[s.z]);
    int f3 = __ldg(&g_feats_pad[s.w]);
    int p;
    p = atomicAdd(&g_pos[d.x], 1); g_csr[p] = make_int2(s.x, f0);
    p = atomicAdd(&g_pos[d.y], 1); g_csr[p] = make_int2(s.y, f1);
    p = atomicAdd(&g_pos[d.z], 1); g_csr[p] = make_int2(s.z, f2);
    p = atomicAdd(&g_pos[d.w], 1); g_csr[p] = make_int2(s.w, f3);
}

// ---------------------------------------------------------------------------
// Unified aggregation:
//   mode=1: z[n] = embh[feat[n]] + sum embh[csr[e].y]
//   mode=0: z[n] = hh[n]        + sum hh[csr[e].x]
// 8 threads/node, one uint4 (8 halves) each, fp32 accumulate, fp16 z out.
// ---------------------------------------------------------------------------
__device__ __forceinline__ void acc8h(float4& A, float4& B, uint4 u) {
    float2 f;
    f = __half22float2(*(const __half2*)&u.x); A.x += f.x; A.y += f.y;
    f = __half22float2(*(const __half2*)&u.y); A.z += f.x; A.w += f.y;
    f = __half22float2(*(const __half2*)&u.z); B.x += f.x; B.y += f.y;
    f = __half22float2(*(const __half2*)&u.w); B.z += f.x; B.w += f.y;
}

__global__ void __launch_bounds__(256)
agg_kernel(int mode) {
    int i = blockIdx.x * blockDim.x + threadIdx.x;
    if (i >= N_NODES * 8) return;
    int n = i >> 3;
    int c = i & 7;
    const uint4* tab = mode ? (const uint4*)g_embh : (const uint4*)g_hh;

    float4 A = {0.f, 0.f, 0.f, 0.f}, B = {0.f, 0.f, 0.f, 0.f};
    int self = mode ? __ldg(&g_feats_pad[n]) : n;
    acc8h(A, B, tab[self * 8 + c]);

    int e   = __ldg(&g_rowptr[n]);
    int end = __ldg(&g_rowptr[n + 1]);
    for (; e < end; e += 8) {
        int4 p0 = *(const int4*)&g_csr[e];
        int4 p1 = *(const int4*)&g_csr[e + 2];
        int4 p2 = *(const int4*)&g_csr[e + 4];
        int4 p3 = *(const int4*)&g_csr[e + 6];
        int s0 = mode ? p0.y : p0.x;
        int s1 = mode ? p0.w : p0.z;
        int s2 = mode ? p1.y : p1.x;
        int s3 = mode ? p1.w : p1.z;
        int s4 = mode ? p2.y : p2.x;
        int s5 = mode ? p2.w : p2.z;
        int s6 = mode ? p3.y : p3.x;
        int s7 = mode ? p3.w : p3.z;
        uint4 u0 = tab[s0 * 8 + c];
        uint4 u1 = tab[s1 * 8 + c];
        uint4 u2 = tab[s2 * 8 + c];
        uint4 u3 = tab[s3 * 8 + c];
        uint4 u4 = tab[s4 * 8 + c];
        uint4 u5 = tab[s5 * 8 + c];
        uint4 u6 = tab[s6 * 8 + c];
        uint4 u7 = tab[s7 * 8 + c];
        acc8h(A, B, u0);
        acc8h(A, B, u1);
        acc8h(A, B, u2);
        acc8h(A, B, u3);
        acc8h(A, B, u4);
        acc8h(A, B, u5);
        acc8h(A, B, u6);
        acc8h(A, B, u7);
    }
    __half2 q0 = __floats2half2_rn(A.x, A.y);
    __half2 q1 = __floats2half2_rn(A.z, A.w);
    __half2 q2 = __floats2half2_rn(B.x, B.y);
    __half2 q3 = __floats2half2_rn(B.z, B.w);
    ((uint4*)g_zh)[n * 8 + c] = make_uint4(*(unsigned*)&q0, *(unsigned*)&q1,
                                           *(unsigned*)&q2, *(unsigned*)&q3);
}

// ---------------------------------------------------------------------------
// MLP via tensor cores (HMMA m16n8k16, fp16 in / fp32 accum):
//   h = relu(z@W1+b1)@W2 + b2.
// 128 threads (4 warps), 128 nodes/block. Warp owns 32 rows x 64 cols.
// GEMM1 C-regs -> relu -> fp16 A-fragments for GEMM2 IN REGISTERS
// (m16n8k16 C layout == A layout identity). LAST layer: fused pool+head.
// ---------------------------------------------------------------------------
#define WS 72   // padded row stride in halves (144B -> conflict-free ldmatrix)

#define LDSM_X4(r0, r1, r2, r3, a) \
    asm volatile("ldmatrix.sync.aligned.m8n8.x4.shared.b16 {%0,%1,%2,%3}, [%4];" \
                 : "=r"(r0), "=r"(r1), "=r"(r2), "=r"(r3) : "r"(a))
#define LDSM_X4T(r0, r1, r2, r3, a) \
    asm volatile("ldmatrix.sync.aligned.m8n8.x4.trans.shared.b16 {%0,%1,%2,%3}, [%4];" \
                 : "=r"(r0), "=r"(r1), "=r"(r2), "=r"(r3) : "r"(a))
#define MMA16816(c, a, b) \
    asm volatile("mma.sync.aligned.m16n8k16.row.col.f32.f16.f16.f32 " \
                 "{%0,%1,%2,%3}, {%4,%5,%6,%7}, {%8,%9}, {%0,%1,%2,%3};" \
                 : "+f"((c)[0]), "+f"((c)[1]), "+f"((c)[2]), "+f"((c)[3]) \
                 : "r"((a)[0]), "r"((a)[1]), "r"((a)[2]), "r"((a)[3]), \
                   "r"((b)[0]), "r"((b)[1]))

__global__ void __launch_bounds__(128)
mlp_kernel(const float* __restrict__ b1, const float* __restrict__ b2,
           int layer, int last,
           const int* __restrict__ gids, const float* __restrict__ Wr,
           float* __restrict__ out) {
    __shared__ __align__(16) __half sW1[HID * WS];
    __shared__ __align__(16) __half sW2[HID * WS];
    __shared__ __align__(16) __half sZ[NPB * WS];

    const int tid  = threadIdx.x;
    const int lane = tid & 31;
    const int w    = tid >> 5;
    const int nbase = blockIdx.x * NPB;

    // ---- stage fp16 weights (padded rows) ----
    {
        const uint4* w1g = (const uint4*)(g_w1h + layer * HID * HID);
        const uint4* w2g = (const uint4*)(g_w2h + layer * HID * HID);
#pragma unroll
        for (int idx = tid; idx < 512; idx += 128) {
            int r = idx >> 3, c = idx & 7;
            *(uint4*)&sW1[r * WS + c * 8] = w1g[idx];
            *(uint4*)&sW2[r * WS + c * 8] = w2g[idx];
        }
    }
    // ---- stage z tile (one 128B row per thread) ----
    {
        int n = nbase + tid;
        if (n < N_NODES) {
            const uint4* zr = (const uint4*)(g_zh + n * HID);
#pragma unroll
            for (int q = 0; q < 8; q++)
                *(uint4*)&sZ[tid * WS + q * 8] = zr[q];
        } else {
            uint4 zz = make_uint4(0u, 0u, 0u, 0u);
#pragma unroll
            for (int q = 0; q < 8; q++)
                *(uint4*)&sZ[tid * WS + q * 8] = zz;
        }
    }
    __syncthreads();

    const float* b1g = b1 + layer * HID;
    const float* b2g = b2 + layer * HID;

    float acc[2][8][4];
    unsigned ya[2][8][2];   // relu(GEMM1) as fp16 A-fragments

    // ================= GEMM 1: Y = relu(Z @ W1 + b1) =================
#pragma unroll
    for (int nt = 0; nt < 8; nt++) {
        int col = nt * 8 + (lane & 3) * 2;
        float v0 = __ldg(b1g + col), v1 = __ldg(b1g + col + 1);
#pragma unroll
        for (int mt = 0; mt < 2; mt++) {
            acc[mt][nt][0] = v0; acc[mt][nt][1] = v1;
            acc[mt][nt][2] = v0; acc[mt][nt][3] = v1;
        }
    }
#pragma unroll
    for (int ks = 0; ks < 4; ks++) {
        unsigned a[2][4], bf[8][2];
#pragma unroll
        for (int mt = 0; mt < 2; mt++) {
            int row = 32 * w + mt * 16 + (lane & 15);
            int ch  = ks * 16 + ((lane >> 4) << 3);
            LDSM_X4(a[mt][0], a[mt][1], a[mt][2], a[mt][3],
                    su32(&sZ[row * WS + ch]));
        }
#pragma unroll
        for (int ntp = 0; ntp < 4; ntp++) {
            int kr = ks * 16 + (((lane >> 3) & 1) << 3) + (lane & 7);
            int nc = ntp * 16 + ((lane >> 4) << 3);
            LDSM_X4T(bf[2 * ntp][0], bf[2 * ntp][1],
                     bf[2 * ntp + 1][0], bf[2 * ntp + 1][1],
                     su32(&sW1[kr * WS + nc]));
        }
#pragma unroll
        for (int mt = 0; mt < 2; mt++)
#pragma unroll
            for (int nt = 0; nt < 8; nt++)
                MMA16816(acc[mt][nt], a[mt], bf[nt]);
    }
    // relu + pack fp16 (C layout == A layout)
#pragma unroll
    for (int mt = 0; mt < 2; mt++)
#pragma unroll
        for (int nt = 0; nt < 8; nt++) {
            __half2 y0 = __floats2half2_rn(fmaxf(acc[mt][nt][0], 0.f),
                                           fmaxf(acc[mt][nt][1], 0.f));
            __half2 y1 = __floats2half2_rn(fmaxf(acc[mt][nt][2], 0.f),
                                           fmaxf(acc[mt][nt][3], 0.f));
            ya[mt][nt][0] = *(unsigned*)&y0;
            ya[mt][nt][1] = *(unsigned*)&y1;
        }

    // ================= GEMM 2: H = Y @ W2 + b2 =================
#pragma unroll
    for (int nt = 0; nt < 8; nt++) {
        int col = nt * 8 + (lane & 3) * 2;
        float v0 = __ldg(b2g + col), v1 = __ldg(b2g + col + 1);
#pragma unroll
        for (int mt = 0; mt < 2; mt++) {
            acc[mt][nt][0] = v0; acc[mt][nt][1] = v1;
            acc[mt][nt][2] = v0; acc[mt][nt][3] = v1;
        }
    }
#pragma unroll
    for (int kt = 0; kt < 4; kt++) {
        unsigned bf[8][2];
#pragma unroll
        for (int ntp = 0; ntp < 4; ntp++) {
            int kr = kt * 16 + (((lane >> 3) & 1) << 3) + (lane & 7);
            int nc = ntp * 16 + ((lane >> 4) << 3);
            LDSM_X4T(bf[2 * ntp][0], bf[2 * ntp][1],
                     bf[2 * ntp + 1][0], bf[2 * ntp + 1][1],
                     su32(&sW2[kr * WS + nc]));
        }
#pragma unroll
        for (int mt = 0; mt < 2; mt++) {
            unsigned a2[4] = { ya[mt][2 * kt][0],     ya[mt][2 * kt][1],
                               ya[mt][2 * kt + 1][0], ya[mt][2 * kt + 1][1] };
#pragma unroll
            for (int nt = 0; nt < 8; nt++)
                MMA16816(acc[mt][nt], a2, bf[nt]);
        }
    }

    if (!last) {
        // store h fp16: thread owns (row0, row0+8) x col pairs per tile
#pragma unroll
        for (int mt = 0; mt < 2; mt++) {
            int row0 = nbase + 32 * w + mt * 16 + (lane >> 2);
#pragma unroll
            for (int nt = 0; nt < 8; nt++) {
                int col = nt * 8 + (lane & 3) * 2;
                if (row0 < N_NODES) {
                    __half2 v = __floats2half2_rn(acc[mt][nt][0], acc[mt][nt][1]);
                    *(__half2*)&g_hh[row0 * HID + col] = v;
                }
                if (row0 + 8 < N_NODES) {
                    __half2 v = __floats2half2_rn(acc[mt][nt][2], acc[mt][nt][3]);
                    *(__half2*)&g_hh[(row0 + 8) * HID + col] = v;
                }
            }
        }
    } else {
        // fused pool + head: dot rows with Wr, reduce over 4 col-lanes
#pragma unroll
        for (int mt = 0; mt < 2; mt++) {
            float d0 = 0.f, d1 = 0.f;
#pragma unroll
            for (int nt = 0; nt < 8; nt++) {
                int col = nt * 8 + (lane & 3) * 2;
                float wr0 = __ldg(Wr + col), wr1 = __ldg(Wr + col + 1);
                d0 = fmaf(acc[mt][nt][0], wr0, fmaf(acc[mt][nt][1], wr1, d0));
                d1 = fmaf(acc[mt][nt][2], wr0, fmaf(acc[mt][nt][3], wr1, d1));
            }
            d0 += __shfl_xor_sync(0xffffffffu, d0, 1);
            d0 += __shfl_xor_sync(0xffffffffu, d0, 2);
            d1 += __shfl_xor_sync(0xffffffffu, d1, 1);
            d1 += __shfl_xor_sync(0xffffffffu, d1, 2);
            if ((lane & 3) == 0) {
                int row0 = nbase + 32 * w + mt * 16 + (lane >> 2);
                if (row0 < N_NODES)
                    atomicAdd(out + __ldg(gids + row0), d0);
                if (row0 + 8 < N_NODES)
                    atomicAdd(out + __ldg(gids + row0 + 8), d1);
            }
        }
    }
}

// ---------------------------------------------------------------------------
extern "C" void kernel_launch(void* const* d_in, const int* in_sizes, int n_in,
                              void* d_out, int out_size) {
    const int*   feats = (const int*)d_in[0];
    const int*   src   = (const int*)d_in[1];
    const int*   dst   = (const int*)d_in[2];
    const int*   gids  = (const int*)d_in[3];
    const float* emb   = (const float*)d_in[4];
    const float* W1    = (const float*)d_in[5];
    const float* b1    = (const float*)d_in[6];
    const float* W2    = (const float*)d_in[7];
    const float* b2    = (const float*)d_in[8];
    const float* Wr    = (const float*)d_in[9];
    float* out = (float*)d_out;

    // CSR build (padded rows) + prep — 3 kernels
    setup_kernel<<<(CSR_CAP / 4 + 255) / 256, 256>>>(dst, feats, emb, W1, W2, out);
    scan_kernel<<<SCAN_BLKS, 1024>>>();
    scatter_kernel<<<(N_EDGES / 4 + 255) / 256, 256>>>(src, dst);

    // 3 GIN layers (agg mode=1 reads emb table; mode=0 reads h)
    const int ablk = (N_NODES * 8 + 255) / 256;
    const int mblk = (N_NODES + NPB - 1) / NPB;

    agg_kernel<<<ablk, 256>>>(1);
    mlp_kernel<<<mblk, 128>>>(b1, b2, 0, 0, gids, Wr, out);
    agg_kernel<<<ablk, 256>>>(0);
    mlp_kernel<<<mblk, 128>>>(b1, b2, 1, 0, gids, Wr, out);
    agg_kernel<<<ablk, 256>>>(0);
    mlp_kernel<<<mblk, 128>>>(b1, b2, 2, 1, gids, Wr, out);
}